// round 3
// baseline (speedup 1.0000x reference)
#include <cuda_runtime.h>
#include <math.h>

// Problem dims (fixed)
#define NB 64     // batch
#define CIN 64    // channels
#define TT 300    // frames
#define VV 25     // joints
#define SS 3      // subsets
#define ICN 16    // inter channels
#define OCN 64    // out channels

// Kernel 1 chunking (scores): TC1 frames per block
#define TC1 10
#define NCH1 (TT / TC1)          // 30 chunks
// Kernel 3 chunking (feature path): TC3 frames per block
#define TC3 5
#define NCH3 (TT / TC3)          // 60 chunks

// Scratch (no allocations allowed) ------------------------------------------
__device__ float g_part[(size_t)NCH1 * NB * SS * VV * VV];  // partial scores, 14.4 MB
__device__ float g_att[(size_t)NB * SS * VV * VV];          // attention, 480 KB

// ============================================================================
// Kernel 1: fused conv_a + conv_b + score accumulation.
// Per block: (n, t-chunk of 10). Computes a=Wa*x+ba, b=Wb*x+bb for all 3
// subsets on the chunk, accumulates partial scores[s][v][u] over (k, t) and
// writes them to g_part (chunk-indexed -> deterministic, no atomics).
// ============================================================================
#define K1_XSTR 256   // padded col stride (250 used)
#define K1_SMEM ((64 * K1_XSTR + 96 * K1_XSTR + 64 * 96) * 4)  // 188416 B

__global__ __launch_bounds__(256, 1)
void k1_scores(const float* __restrict__ x, const float* __restrict__ wa,
               const float* __restrict__ ba, const float* __restrict__ wb,
               const float* __restrict__ bb)
{
    const int n   = blockIdx.x;
    const int ch  = blockIdx.y;
    const int t0  = ch * TC1;
    const int tid = threadIdx.x;
    const int lane = tid & 31;
    const int wrp  = tid >> 5;

    extern __shared__ float sm[];
    float* x_sm  = sm;                       // [64][256]  (250 cols used, zero pad)
    float* ab_sm = x_sm + 64 * K1_XSTR;      // [96][256]  rows 0..47 = a, 48..95 = b
    float* w_sm  = ab_sm + 96 * K1_XSTR;     // [64][96]   w_sm[c*96 + row]

    // Load stacked weights: row<48 -> wa[s,k,c] (row = s*16+k), else wb
    for (int i = tid; i < 64 * 96; i += 256) {
        int c = i / 96, row = i % 96;
        w_sm[c * 96 + row] = (row < 48) ? wa[row * 64 + c] : wb[(row - 48) * 64 + c];
    }
    // Load x chunk: x[n, c, t0..t0+9, :] -> x_sm[c][j], j = dt*25+v, pad->0
    const float* xg = x + (size_t)n * 64 * 7500 + (size_t)t0 * 25;
    for (int i = tid; i < 64 * K1_XSTR; i += 256) {
        int c = i >> 8, j = i & 255;
        x_sm[i] = (j < 250) ? xg[(size_t)c * 7500 + j] : 0.f;
    }
    __syncthreads();

    // Phase 1: conv GEMM — 96 rows x 250 cols, K = 64. Bias folded into init.
    {
        const int r0 = wrp * 12;
        float acc[12][8];
        #pragma unroll
        for (int r = 0; r < 12; r++) {
            int row = r0 + r;
            float bias = (row < 48) ? ba[row] : bb[row - 48];
            #pragma unroll
            for (int q = 0; q < 8; q++) acc[r][q] = bias;
        }
        for (int k = 0; k < 64; k++) {
            float xv[8];
            #pragma unroll
            for (int q = 0; q < 8; q++) xv[q] = x_sm[k * K1_XSTR + lane + 32 * q];
            #pragma unroll
            for (int r = 0; r < 12; r++) {
                float wv = w_sm[k * 96 + r0 + r];
                #pragma unroll
                for (int q = 0; q < 8; q++)
                    acc[r][q] = fmaf(wv, xv[q], acc[r][q]);
            }
        }
        #pragma unroll
        for (int r = 0; r < 12; r++)
            #pragma unroll
            for (int q = 0; q < 8; q++)
                ab_sm[(r0 + r) * K1_XSTR + lane + 32 * q] = acc[r][q];
    }
    __syncthreads();

    // Phase 2: partial scores[s][v][u] = sum_{k<16, tt<10} a[k,tt,v]*b[k,tt,u]
    // warp handles (s,v) pairs; lane = u (lanes 25..31 idle).
    const float inv = 1.0f / (float)(ICN * TT);   // 1/4800
    for (int p = wrp; p < SS * VV; p += 8) {
        int s = p / 25, v = p % 25;
        const float* arow0 = ab_sm + (s * 16) * K1_XSTR;
        const float* brow0 = ab_sm + (48 + s * 16) * K1_XSTR;
        float accs = 0.f;
        for (int kk = 0; kk < 16; kk++) {
            const float* ar = arow0 + kk * K1_XSTR;
            const float* br = brow0 + kk * K1_XSTR;
            #pragma unroll
            for (int dt = 0; dt < TC1; dt++) {
                float av = ar[dt * 25 + v];                   // broadcast
                accs = fmaf(av, br[dt * 25 + lane], accs);    // coalesced
            }
        }
        if (lane < 25)
            g_part[(((size_t)ch * NB + n) * SS + s) * 625 + v * 25 + lane] = accs * inv;
    }
}

// ============================================================================
// Kernel 2: reduce chunk partials, softmax over v (axis -2), add A+PA -> g_att
// ============================================================================
__global__ void k2_softmax(const float* __restrict__ A, const float* __restrict__ PA)
{
    const int n = blockIdx.x, s = blockIdx.y;
    __shared__ float sc[625];
    const int tid = threadIdx.x;

    for (int i = tid; i < 625; i += 256) {
        float acc = 0.f;
        for (int ch = 0; ch < NCH1; ch++)
            acc += g_part[(((size_t)ch * NB + n) * SS + s) * 625 + i];
        sc[i] = acc;
    }
    __syncthreads();

    if (tid < 25) {
        const int u = tid;
        float mx = -1e30f;
        #pragma unroll
        for (int v = 0; v < 25; v++) mx = fmaxf(mx, sc[v * 25 + u]);
        float e[25], sum = 0.f;
        #pragma unroll
        for (int v = 0; v < 25; v++) { e[v] = expf(sc[v * 25 + u] - mx); sum += e[v]; }
        const float rs = 1.f / sum;
        #pragma unroll
        for (int v = 0; v < 25; v++) {
            int idx = s * 625 + v * 25 + u;
            g_att[((size_t)n * SS + s) * 625 + v * 25 + u] = e[v] * rs + A[idx] + PA[idx];
        }
    }
}

// ============================================================================
// Kernel 3: fused y = x@att (per subset), z = conv_d(y) summed over subsets,
// BatchNorm (inference), residual with x (already in SMEM), ReLU, store.
// Per block: (n, t-chunk of 5) -> 125 columns of (t,v).
// ============================================================================
#define K3_CSTR 128   // padded col stride (125 used)
#define K3_SMEM ((64 * K3_CSTR + 192 * K3_CSTR + 192 * 64 + 3 * 632 + 128) * 4)  // 188320 B

__global__ __launch_bounds__(256, 1)
void k3_fused(const float* __restrict__ x, const float* __restrict__ wd,
              const float* __restrict__ bd,
              const float* __restrict__ gma, const float* __restrict__ bta,
              const float* __restrict__ mu,  const float* __restrict__ var,
              float* __restrict__ out)
{
    const int n   = blockIdx.x;
    const int ch  = blockIdx.y;
    const int t0  = ch * TC3;
    const int tid = threadIdx.x;
    const int lane = tid & 31;
    const int wrp  = tid >> 5;

    extern __shared__ float sm[];
    float* x_sm   = sm;                        // [64][128]  (125 used)
    float* y_sm   = x_sm + 64 * K3_CSTR;       // [192][128] rows = s*64+c
    float* w_sm   = y_sm + 192 * K3_CSTR;      // [192][64]  w_sm[k*64+o] = wd[s,o,c], k=s*64+c
    float* att_sm = w_sm + 192 * 64;           // [3][632]
    float* scale_sm = att_sm + 3 * 632;        // [64]
    float* shift_sm = scale_sm + 64;           // [64]

    // Loads ------------------------------------------------------------------
    const float* xg = x + (size_t)n * 64 * 7500 + (size_t)t0 * 25;
    for (int i = tid; i < 64 * K3_CSTR; i += 256) {
        int c = i >> 7, j = i & 127;
        x_sm[i] = (j < 125) ? xg[(size_t)c * 7500 + j] : 0.f;
    }
    for (int i = tid; i < 192 * 64; i += 256) {
        int k = i >> 6, o = i & 63;
        int s = k >> 6, c = k & 63;
        w_sm[i] = wd[((size_t)(s * 64 + o)) * 64 + c];
    }
    for (int i = tid; i < SS * 625; i += 256) {
        int s = i / 625, r = i % 625;
        att_sm[s * 632 + r] = g_att[((size_t)n * SS + s) * 625 + r];
    }
    for (int i = tid; i < 192; i += 256) {   // zero pad cols 125..127 of y
        y_sm[i * K3_CSTR + 125] = 0.f;
        y_sm[i * K3_CSTR + 126] = 0.f;
        y_sm[i * K3_CSTR + 127] = 0.f;
    }
    if (tid < 64) {
        float scl = gma[tid] * rsqrtf(var[tid] + 1e-5f);
        float bsum = bd[tid] + bd[64 + tid] + bd[128 + tid];
        scale_sm[tid] = scl;
        shift_sm[tid] = (bsum - mu[tid]) * scl + bta[tid];
    }
    __syncthreads();

    // Phase Y: y[s,c,tt,u] = sum_v x[c,tt,v] * att[s][v][u]; att cached in regs
    for (int s = 0; s < SS; s++) {
        float areg[25];
        #pragma unroll
        for (int v = 0; v < 25; v++)
            areg[v] = (lane < 25) ? att_sm[s * 632 + v * 25 + lane] : 0.f;
        for (int rr = wrp; rr < 64 * TC3; rr += 8) {
            int c = rr / TC3, dt = rr % TC3;
            const float* xr = x_sm + c * K3_CSTR + dt * 25;
            float acc = 0.f;
            #pragma unroll
            for (int v = 0; v < 25; v++)
                acc = fmaf(xr[v], areg[v], acc);
            if (lane < 25)
                y_sm[(s * 64 + c) * K3_CSTR + dt * 25 + lane] = acc;
        }
    }
    __syncthreads();

    // Phase Z: GEMM 64x125, K=192 (conv_d + sum over subsets), then BN+res+ReLU
    {
        const int o0 = wrp * 8;
        float acc[8][4];
        #pragma unroll
        for (int r = 0; r < 8; r++)
            #pragma unroll
            for (int q = 0; q < 4; q++) acc[r][q] = 0.f;

        for (int k = 0; k < 192; k++) {
            float4 w0 = *(const float4*)(w_sm + k * 64 + o0);
            float4 w1 = *(const float4*)(w_sm + k * 64 + o0 + 4);
            float wr[8] = {w0.x, w0.y, w0.z, w0.w, w1.x, w1.y, w1.z, w1.w};
            float yv[4];
            #pragma unroll
            for (int q = 0; q < 4; q++) yv[q] = y_sm[k * K3_CSTR + lane + 32 * q];
            #pragma unroll
            for (int r = 0; r < 8; r++)
                #pragma unroll
                for (int q = 0; q < 4; q++)
                    acc[r][q] = fmaf(wr[r], yv[q], acc[r][q]);
        }

        float* og = out + (size_t)n * 64 * 7500 + (size_t)t0 * 25;
        #pragma unroll
        for (int r = 0; r < 8; r++) {
            int o = o0 + r;
            float scl = scale_sm[o], shf = shift_sm[o];
            #pragma unroll
            for (int q = 0; q < 4; q++) {
                int j = lane + 32 * q;
                if (j < 125) {
                    float zn  = acc[r][q] * scl + shf;
                    float res = zn + x_sm[o * K3_CSTR + j];
                    og[(size_t)o * 7500 + j] = fmaxf(res, 0.f);
                }
            }
        }
    }
}

// ============================================================================
extern "C" void kernel_launch(void* const* d_in, const int* in_sizes, int n_in,
                              void* d_out, int out_size)
{
    const float* x   = (const float*)d_in[0];
    const float* A   = (const float*)d_in[1];
    const float* PA  = (const float*)d_in[2];
    const float* wa  = (const float*)d_in[3];
    const float* ba  = (const float*)d_in[4];
    const float* wb  = (const float*)d_in[5];
    const float* bb  = (const float*)d_in[6];
    const float* wd  = (const float*)d_in[7];
    const float* bd  = (const float*)d_in[8];
    const float* gma = (const float*)d_in[9];
    const float* bta = (const float*)d_in[10];
    const float* mu  = (const float*)d_in[11];
    const float* var = (const float*)d_in[12];
    float* out = (float*)d_out;

    cudaFuncSetAttribute(k1_scores, cudaFuncAttributeMaxDynamicSharedMemorySize, K1_SMEM);
    cudaFuncSetAttribute(k3_fused,  cudaFuncAttributeMaxDynamicSharedMemorySize, K3_SMEM);

    k1_scores<<<dim3(NB, NCH1), 256, K1_SMEM>>>(x, wa, ba, wb, bb);
    k2_softmax<<<dim3(NB, SS), 256>>>(A, PA);
    k3_fused<<<dim3(NB, NCH3), 256, K3_SMEM>>>(x, wd, bd, gma, bta, mu, var, out);
}

// round 4
// speedup vs baseline: 1.1320x; 1.1320x over previous
#include <cuda_runtime.h>
#include <math.h>

// Problem dims (fixed)
#define NB 64     // batch
#define CIN 64    // channels
#define TT 300    // frames
#define VV 25     // joints
#define SS 3      // subsets
#define ICN 16    // inter channels
#define OCN 64    // out channels

// Kernel 1 chunking (scores): TC1 frames per block
#define TC1 10
#define NCH1 (TT / TC1)          // 30 chunks
// Kernel 3 chunking (feature path): TC3 frames per block
#define TC3 5
#define NCH3 (TT / TC3)          // 60 chunks

// Scratch (no allocations allowed) ------------------------------------------
__device__ float g_part[(size_t)NCH1 * NB * SS * VV * VV];  // partial scores, 14.4 MB
__device__ float g_att[(size_t)NB * SS * VV * VV];          // attention, 480 KB

// ============================================================================
// Kernel 1: fused conv_a + conv_b + score accumulation. 512 threads/CTA.
// ============================================================================
#define K1_XSTR 256   // padded col stride (250 used)
#define K1_SMEM ((64 * K1_XSTR + 96 * K1_XSTR + 64 * 96) * 4)  // 188416 B

__global__ __launch_bounds__(512, 1)
void k1_scores(const float* __restrict__ x, const float* __restrict__ wa,
               const float* __restrict__ ba, const float* __restrict__ wb,
               const float* __restrict__ bb)
{
    const int n   = blockIdx.x;
    const int ch  = blockIdx.y;
    const int t0  = ch * TC1;
    const int tid = threadIdx.x;
    const int lane = tid & 31;
    const int wrp  = tid >> 5;          // 0..15

    extern __shared__ float sm[];
    float* x_sm  = sm;                       // [64][256]  (250 cols used, zero pad)
    float* ab_sm = x_sm + 64 * K1_XSTR;      // [96][256]  rows 0..47 = a, 48..95 = b
    float* w_sm  = ab_sm + 96 * K1_XSTR;     // [64][96]   w_sm[c*96 + row]

    // Load stacked weights: row<48 -> wa[s,k,c] (row = s*16+k), else wb
    for (int i = tid; i < 64 * 96; i += 512) {
        int c = i / 96, row = i % 96;
        w_sm[c * 96 + row] = (row < 48) ? wa[row * 64 + c] : wb[(row - 48) * 64 + c];
    }
    // Load x chunk: x[n, c, t0..t0+9, :] -> x_sm[c][j], j = dt*25+v, pad->0
    const float* xg = x + (size_t)n * 64 * 7500 + (size_t)t0 * 25;
    for (int i = tid; i < 64 * K1_XSTR; i += 512) {
        int c = i >> 8, j = i & 255;
        x_sm[i] = (j < 250) ? xg[(size_t)c * 7500 + j] : 0.f;
    }
    __syncthreads();

    // Phase 1: conv GEMM — 96 rows x 250 cols, K = 64. 16 warps x 6 rows.
    {
        const int r0 = wrp * 6;
        float acc[6][8];
        #pragma unroll
        for (int r = 0; r < 6; r++) {
            int row = r0 + r;
            float bias = (row < 48) ? ba[row] : bb[row - 48];
            #pragma unroll
            for (int q = 0; q < 8; q++) acc[r][q] = bias;
        }
        for (int k = 0; k < 64; k++) {
            float xv[8];
            #pragma unroll
            for (int q = 0; q < 8; q++) xv[q] = x_sm[k * K1_XSTR + lane + 32 * q];
            #pragma unroll
            for (int r = 0; r < 6; r++) {
                float wv = w_sm[k * 96 + r0 + r];
                #pragma unroll
                for (int q = 0; q < 8; q++)
                    acc[r][q] = fmaf(wv, xv[q], acc[r][q]);
            }
        }
        #pragma unroll
        for (int r = 0; r < 6; r++)
            #pragma unroll
            for (int q = 0; q < 8; q++)
                ab_sm[(r0 + r) * K1_XSTR + lane + 32 * q] = acc[r][q];
    }
    __syncthreads();

    // Phase 2: partial scores[s][v][u] = sum_{k<16, tt<10} a[k,tt,v]*b[k,tt,u]
    // 15 tasks: (s, v-strip of 5). lane = u. One coalesced b-load reused x5.
    const float inv = 1.0f / (float)(ICN * TT);   // 1/4800
    for (int task = wrp; task < SS * 5; task += 16) {
        int s = task / 5, v0 = (task % 5) * 5;
        const float* arow0 = ab_sm + (s * 16) * K1_XSTR;
        const float* brow0 = ab_sm + (48 + s * 16) * K1_XSTR;
        float acc[5] = {0.f, 0.f, 0.f, 0.f, 0.f};
        for (int kk = 0; kk < 16; kk++) {
            const float* ar = arow0 + kk * K1_XSTR;
            const float* br = brow0 + kk * K1_XSTR;
            #pragma unroll
            for (int dt = 0; dt < TC1; dt++) {
                float bv = br[dt * 25 + lane];                // coalesced
                #pragma unroll
                for (int i = 0; i < 5; i++)
                    acc[i] = fmaf(ar[dt * 25 + v0 + i], bv, acc[i]);
            }
        }
        if (lane < 25) {
            float* dst = g_part + (((size_t)ch * NB + n) * SS + s) * 625;
            #pragma unroll
            for (int i = 0; i < 5; i++)
                dst[(v0 + i) * 25 + lane] = acc[i] * inv;
        }
    }
}

// ============================================================================
// Kernel 2: reduce chunk partials, softmax over v (axis -2), add A+PA -> g_att
// ============================================================================
__global__ void k2_softmax(const float* __restrict__ A, const float* __restrict__ PA)
{
    const int n = blockIdx.x, s = blockIdx.y;
    __shared__ float sc[625];
    const int tid = threadIdx.x;

    for (int i = tid; i < 625; i += 256) {
        float acc = 0.f;
        for (int ch = 0; ch < NCH1; ch++)
            acc += g_part[(((size_t)ch * NB + n) * SS + s) * 625 + i];
        sc[i] = acc;
    }
    __syncthreads();

    if (tid < 25) {
        const int u = tid;
        float mx = -1e30f;
        #pragma unroll
        for (int v = 0; v < 25; v++) mx = fmaxf(mx, sc[v * 25 + u]);
        float e[25], sum = 0.f;
        #pragma unroll
        for (int v = 0; v < 25; v++) { e[v] = expf(sc[v * 25 + u] - mx); sum += e[v]; }
        const float rs = 1.f / sum;
        #pragma unroll
        for (int v = 0; v < 25; v++) {
            int idx = s * 625 + v * 25 + u;
            g_att[((size_t)n * SS + s) * 625 + v * 25 + u] = e[v] * rs + A[idx] + PA[idx];
        }
    }
}

// ============================================================================
// Kernel 3: fused y = x@att, z = conv_d(y) summed over s, BN, residual, ReLU.
// 512 threads/CTA. Per block: (n, t-chunk of 5) -> 125 (t,v) columns.
// ============================================================================
#define K3_CSTR 128   // padded col stride (125 used)
#define K3_SMEM ((64 * K3_CSTR + 192 * K3_CSTR + 192 * 64 + 3 * 632 + 128) * 4)  // 188320 B

__global__ __launch_bounds__(512, 1)
void k3_fused(const float* __restrict__ x, const float* __restrict__ wd,
              const float* __restrict__ bd,
              const float* __restrict__ gma, const float* __restrict__ bta,
              const float* __restrict__ mu,  const float* __restrict__ var,
              float* __restrict__ out)
{
    const int n   = blockIdx.x;
    const int ch  = blockIdx.y;
    const int t0  = ch * TC3;
    const int tid = threadIdx.x;
    const int lane = tid & 31;
    const int wrp  = tid >> 5;          // 0..15

    extern __shared__ float sm[];
    float* x_sm   = sm;                        // [64][128]  (125 used)
    float* y_sm   = x_sm + 64 * K3_CSTR;       // [192][128] rows = s*64+c
    float* w_sm   = y_sm + 192 * K3_CSTR;      // [192][64]  w_sm[k*64+o] = wd[s,o,c], k=s*64+c
    float* att_sm = w_sm + 192 * 64;           // [3][632]
    float* scale_sm = att_sm + 3 * 632;        // [64]
    float* shift_sm = scale_sm + 64;           // [64]

    // Loads ------------------------------------------------------------------
    const float* xg = x + (size_t)n * 64 * 7500 + (size_t)t0 * 25;
    for (int i = tid; i < 64 * K3_CSTR; i += 512) {
        int c = i >> 7, j = i & 127;
        x_sm[i] = (j < 125) ? xg[(size_t)c * 7500 + j] : 0.f;
    }
    for (int i = tid; i < 192 * 64; i += 512) {
        int k = i >> 6, o = i & 63;
        int s = k >> 6, c = k & 63;
        w_sm[i] = wd[((size_t)(s * 64 + o)) * 64 + c];
    }
    for (int i = tid; i < SS * 625; i += 512) {
        int s = i / 625, r = i % 625;
        att_sm[s * 632 + r] = g_att[((size_t)n * SS + s) * 625 + r];
    }
    if (tid < 192) {   // zero pad cols 125..127 of y
        y_sm[tid * K3_CSTR + 125] = 0.f;
        y_sm[tid * K3_CSTR + 126] = 0.f;
        y_sm[tid * K3_CSTR + 127] = 0.f;
    }
    if (tid < 64) {
        float scl = gma[tid] * rsqrtf(var[tid] + 1e-5f);
        float bsum = bd[tid] + bd[64 + tid] + bd[128 + tid];
        scale_sm[tid] = scl;
        shift_sm[tid] = (bsum - mu[tid]) * scl + bta[tid];
    }
    __syncthreads();

    // Phase Y: y[s,c,tt,u] = sum_v x[c,tt,v] * att[s][v][u]; att cached in regs
    for (int s = 0; s < SS; s++) {
        float areg[25];
        #pragma unroll
        for (int v = 0; v < 25; v++)
            areg[v] = (lane < 25) ? att_sm[s * 632 + v * 25 + lane] : 0.f;
        for (int rr = wrp; rr < 64 * TC3; rr += 16) {
            int c = rr / TC3, dt = rr % TC3;
            const float* xr = x_sm + c * K3_CSTR + dt * 25;
            float acc = 0.f;
            #pragma unroll
            for (int v = 0; v < 25; v++)
                acc = fmaf(xr[v], areg[v], acc);
            if (lane < 25)
                y_sm[(s * 64 + c) * K3_CSTR + dt * 25 + lane] = acc;
        }
    }
    __syncthreads();

    // Phase Z: GEMM 64x125, K=192 (conv_d + subset sum), then BN+res+ReLU.
    // 16 warps: 8 row-groups x 2 column-halves.
    {
        const int o0   = (wrp >> 1) * 8;
        const int half = wrp & 1;            // cols lane+64*half, lane+32+64*half
        float acc[8][2];
        #pragma unroll
        for (int r = 0; r < 8; r++) { acc[r][0] = 0.f; acc[r][1] = 0.f; }

        const int j0 = lane + 64 * half;
        for (int k = 0; k < 192; k++) {
            float4 w0 = *(const float4*)(w_sm + k * 64 + o0);
            float4 w1 = *(const float4*)(w_sm + k * 64 + o0 + 4);
            float wr[8] = {w0.x, w0.y, w0.z, w0.w, w1.x, w1.y, w1.z, w1.w};
            float y0 = y_sm[k * K3_CSTR + j0];
            float y1 = y_sm[k * K3_CSTR + j0 + 32];
            #pragma unroll
            for (int r = 0; r < 8; r++) {
                acc[r][0] = fmaf(wr[r], y0, acc[r][0]);
                acc[r][1] = fmaf(wr[r], y1, acc[r][1]);
            }
        }

        float* og = out + (size_t)n * 64 * 7500 + (size_t)t0 * 25;
        #pragma unroll
        for (int r = 0; r < 8; r++) {
            int o = o0 + r;
            float scl = scale_sm[o], shf = shift_sm[o];
            #pragma unroll
            for (int q = 0; q < 2; q++) {
                int j = j0 + 32 * q;
                if (j < 125) {
                    float zn  = acc[r][q] * scl + shf;
                    float res = zn + x_sm[o * K3_CSTR + j];
                    og[(size_t)o * 7500 + j] = fmaxf(res, 0.f);
                }
            }
        }
    }
}

// ============================================================================
extern "C" void kernel_launch(void* const* d_in, const int* in_sizes, int n_in,
                              void* d_out, int out_size)
{
    const float* x   = (const float*)d_in[0];
    const float* A   = (const float*)d_in[1];
    const float* PA  = (const float*)d_in[2];
    const float* wa  = (const float*)d_in[3];
    const float* ba  = (const float*)d_in[4];
    const float* wb  = (const float*)d_in[5];
    const float* bb  = (const float*)d_in[6];
    const float* wd  = (const float*)d_in[7];
    const float* bd  = (const float*)d_in[8];
    const float* gma = (const float*)d_in[9];
    const float* bta = (const float*)d_in[10];
    const float* mu  = (const float*)d_in[11];
    const float* var = (const float*)d_in[12];
    float* out = (float*)d_out;

    cudaFuncSetAttribute(k1_scores, cudaFuncAttributeMaxDynamicSharedMemorySize, K1_SMEM);
    cudaFuncSetAttribute(k3_fused,  cudaFuncAttributeMaxDynamicSharedMemorySize, K3_SMEM);

    k1_scores<<<dim3(NB, NCH1), 512, K1_SMEM>>>(x, wa, ba, wb, bb);
    k2_softmax<<<dim3(NB, SS), 256>>>(A, PA);
    k3_fused<<<dim3(NB, NCH3), 512, K3_SMEM>>>(x, wd, bd, gma, bta, mu, var, out);
}

// round 5
// speedup vs baseline: 1.4404x; 1.2724x over previous
#include <cuda_runtime.h>
#include <math.h>

// Problem dims (fixed)
#define NB 64
#define TT 300
#define VV 25
#define SS 3

#define TC1 5
#define NCH1 (TT / TC1)          // 60 chunks for k1
#define TC3 5
#define NCH3 (TT / TC3)          // 60 chunks for k3

// Scratch (no allocations allowed)
__device__ float g_part[(size_t)NCH1 * NB * SS * VV * VV];  // 28.8 MB
__device__ float g_att[(size_t)NB * SS * VV * VV];          // 480 KB

// ---- packed f32x2 helpers (PTX-only; ptxas never auto-fuses FFMA2) --------
typedef unsigned long long u64t;
__device__ __forceinline__ u64t pk2(float a, float b) {
    u64t d; asm("mov.b64 %0,{%1,%2};" : "=l"(d) : "f"(a), "f"(b)); return d;
}
__device__ __forceinline__ void fma2(u64t& d, u64t a, u64t b) {
    asm("fma.rn.f32x2 %0,%1,%2,%0;" : "+l"(d) : "l"(a), "l"(b));
}
__device__ __forceinline__ float2 up2(u64t d) {
    float lo, hi; asm("mov.b64 {%0,%1},%2;" : "=f"(lo), "=f"(hi) : "l"(d));
    return make_float2(lo, hi);
}

// ============================================================================
// Kernel 1: fused conv_a + conv_b + partial score accumulation.
// 512 threads, TC1=5 frames/block, smem 106.5 KB -> 2 CTAs/SM.
// Phase 1 packs FMAs over ROW pairs (w-pairs load directly as LDS.64).
// ============================================================================
#define K1_XS 128   // x / ab column stride (125 used)
#define K1_NF (64 * K1_XS + 96 * K1_XS + 64 * 16 * 6)   // 26624 floats
#define K1_SMEM (K1_NF * 4)                              // 106496 B

__global__ __launch_bounds__(512, 2)
void k1_scores(const float* __restrict__ x, const float* __restrict__ wa,
               const float* __restrict__ ba, const float* __restrict__ wb,
               const float* __restrict__ bb)
{
    const int n = blockIdx.x, ch = blockIdx.y, t0 = ch * TC1;
    const int tid = threadIdx.x, lane = tid & 31, wrp = tid >> 5;  // 16 warps

    extern __shared__ float sm[];
    float* x_sm  = sm;                       // [64][128]
    float* ab_sm = x_sm + 64 * K1_XS;        // [96][128] rows 0..47 a, 48..95 b
    float* w_sm  = ab_sm + 96 * K1_XS;       // [k][warp][6] : base (k*16+w)*6

    // weights: w_sm[(k*16+w)*6 + r] = stacked[row = w*6+r][k]
    for (int i = tid; i < 64 * 96; i += 512) {
        int k = i / 96, slot = i % 96, w = slot / 6, r = slot % 6;
        int row = w * 6 + r;
        w_sm[(k * 16 + w) * 6 + r] =
            (row < 48) ? wa[row * 64 + k] : wb[(row - 48) * 64 + k];
    }
    const float* xg = x + (size_t)n * 64 * 7500 + (size_t)t0 * 25;
    for (int i = tid; i < 64 * K1_XS; i += 512) {
        int c = i >> 7, j = i & 127;
        x_sm[i] = (j < 125) ? xg[(size_t)c * 7500 + j] : 0.f;
    }
    __syncthreads();

    // Phase 1: 96 rows x 128 cols, K=64. Warp = 6 rows (3 row-pairs), 4 cols/thr.
    {
        const int r0 = wrp * 6;
        u64t acc[3][4];
        #pragma unroll
        for (int p = 0; p < 3; p++) {
            int ra = r0 + 2 * p, rb = ra + 1;
            float bA = (ra < 48) ? ba[ra] : bb[ra - 48];
            float bB = (rb < 48) ? ba[rb] : bb[rb - 48];
            u64t bi = pk2(bA, bB);
            #pragma unroll
            for (int q = 0; q < 4; q++) acc[p][q] = bi;
        }
        #pragma unroll 4
        for (int k = 0; k < 64; k++) {
            const float* wp = w_sm + (k * 16 + wrp) * 6;
            u64t w0 = *(const u64t*)(wp);        // {row r0,   r0+1}
            u64t w1 = *(const u64t*)(wp + 2);    // {row r0+2, r0+3}
            u64t w2 = *(const u64t*)(wp + 4);    // {row r0+4, r0+5}
            #pragma unroll
            for (int q = 0; q < 4; q++) {
                float xv = x_sm[k * K1_XS + lane + 32 * q];
                u64t xq = pk2(xv, xv);
                fma2(acc[0][q], w0, xq);
                fma2(acc[1][q], w1, xq);
                fma2(acc[2][q], w2, xq);
            }
        }
        #pragma unroll
        for (int p = 0; p < 3; p++)
            #pragma unroll
            for (int q = 0; q < 4; q++) {
                float2 f = up2(acc[p][q]);
                int col = lane + 32 * q;
                ab_sm[(r0 + 2 * p)     * K1_XS + col] = f.x;
                ab_sm[(r0 + 2 * p + 1) * K1_XS + col] = f.y;
            }
    }
    __syncthreads();

    // Phase 2: partial scores over (k<16, dt<5). 15 tasks (s, v-strip of 5).
    const float inv = 1.0f / 4800.0f;
    for (int task = wrp; task < SS * 5; task += 16) {
        int s = task / 5, v0 = (task % 5) * 5;
        const float* arow0 = ab_sm + (s * 16) * K1_XS;
        const float* brow0 = ab_sm + (48 + s * 16) * K1_XS;
        float acc[5] = {0.f, 0.f, 0.f, 0.f, 0.f};
        for (int kk = 0; kk < 16; kk++) {
            const float* ar = arow0 + kk * K1_XS;
            const float* br = brow0 + kk * K1_XS;
            #pragma unroll
            for (int dt = 0; dt < TC1; dt++) {
                float bv = br[dt * 25 + lane];
                #pragma unroll
                for (int i = 0; i < 5; i++)
                    acc[i] = fmaf(ar[dt * 25 + v0 + i], bv, acc[i]);
            }
        }
        if (lane < 25) {
            float* dst = g_part + (((size_t)ch * NB + n) * SS + s) * 625;
            #pragma unroll
            for (int i = 0; i < 5; i++)
                dst[(v0 + i) * 25 + lane] = acc[i] * inv;
        }
    }
}

// ============================================================================
// Kernel 2: reduce chunk partials, softmax over v, add A+PA -> g_att
// ============================================================================
__global__ void k2_softmax(const float* __restrict__ A, const float* __restrict__ PA)
{
    const int n = blockIdx.x, s = blockIdx.y;
    __shared__ float sc[625];
    const int tid = threadIdx.x;

    for (int i = tid; i < 625; i += 256) {
        float acc = 0.f;
        for (int ch = 0; ch < NCH1; ch++)
            acc += g_part[(((size_t)ch * NB + n) * SS + s) * 625 + i];
        sc[i] = acc;
    }
    __syncthreads();

    if (tid < 25) {
        const int u = tid;
        float mx = -1e30f;
        #pragma unroll
        for (int v = 0; v < 25; v++) mx = fmaxf(mx, sc[v * 25 + u]);
        float e[25], sum = 0.f;
        #pragma unroll
        for (int v = 0; v < 25; v++) { e[v] = expf(sc[v * 25 + u] - mx); sum += e[v]; }
        const float rs = 1.f / sum;
        #pragma unroll
        for (int v = 0; v < 25; v++) {
            int idx = s * 625 + v * 25 + u;
            g_att[((size_t)n * SS + s) * 625 + v * 25 + u] = e[v] * rs + A[idx] + PA[idx];
        }
    }
}

// ============================================================================
// Kernel 3: subset-sequential fused y = x@att_s -> z += wd_s@y, then
// BN + residual + ReLU. 512 threads, smem ~91 KB -> 2 CTAs/SM.
// Phase Y packs over v (x padded to 28/row for aligned pair loads).
// Phase Z packs over o (w-pairs load directly as v2.u64).
// ============================================================================
#define K3_XPAD 28                         // v padded 25 -> 28 (even, 16B-friendly)
#define K3_XSTR (TC3 * K3_XPAD)            // 140 floats per channel row
#define K3_NF (64 * K3_XSTR + 64 * 128 + 64 * 64 + 3 * 632 + 128)  // 23272 floats
#define K3_SMEM (K3_NF * 4)                                         // 93088 B

__global__ __launch_bounds__(512, 2)
void k3_fused(const float* __restrict__ x, const float* __restrict__ wd,
              const float* __restrict__ bd,
              const float* __restrict__ gma, const float* __restrict__ bta,
              const float* __restrict__ mu,  const float* __restrict__ var,
              float* __restrict__ out)
{
    const int n = blockIdx.x, ch = blockIdx.y, t0 = ch * TC3;
    const int tid = threadIdx.x, lane = tid & 31, wrp = tid >> 5;

    extern __shared__ float sm[];
    float* x_sm   = sm;                          // [64][140]  (dt*28+v layout)
    float* y_sm   = x_sm + 64 * K3_XSTR;         // [64][128]  one subset
    float* w_sm   = y_sm + 64 * 128;             // [64][64]   w_sm[k*64+o], one subset
    float* att_sm = w_sm + 64 * 64;              // [3][632]
    float* sc_sm  = att_sm + 3 * 632;            // [64]
    float* sh_sm  = sc_sm + 64;                  // [64]

    const float* xg = x + (size_t)n * 64 * 7500 + (size_t)t0 * 25;
    for (int i = tid; i < 64 * 125; i += 512) {
        int c = i / 125, j = i % 125, dt = j / 25, v = j % 25;
        x_sm[c * K3_XSTR + dt * K3_XPAD + v] = xg[(size_t)c * 7500 + j];
    }
    for (int i = tid; i < SS * 625; i += 512) {
        int s = i / 625, r = i % 625;
        att_sm[s * 632 + r] = g_att[((size_t)n * SS + s) * 625 + r];
    }
    if (tid < 64) {
        float scl = gma[tid] * rsqrtf(var[tid] + 1e-5f);
        float bsum = bd[tid] + bd[64 + tid] + bd[128 + tid];
        sc_sm[tid] = scl;
        sh_sm[tid] = (bsum - mu[tid]) * scl + bta[tid];
    }

    const int o0 = (wrp >> 1) * 8;      // 8-row o-group
    const int half = wrp & 1;
    const int j0 = lane + 64 * half;    // cols j0, j0+32
    u64t zacc[8];                       // [q*4 + pair] : o-pairs x 2 cols
    #pragma unroll
    for (int r = 0; r < 8; r++) zacc[r] = 0ULL;

    for (int s = 0; s < SS; s++) {
        __syncthreads();   // y_sm/w_sm free (also covers initial loads on s=0)

        // load this subset's conv_d weights transposed: w_sm[k*64+o] = wd[s,o,k]
        for (int i = tid; i < 4096; i += 512) {
            int k = i >> 6, o = i & 63;
            w_sm[i] = wd[(size_t)s * 4096 + o * 64 + k];
        }

        // Phase Y: y[c][dt*25+u] = sum_v x[c][dt][v] * att_s[v][u]
        {
            const int u = (lane < 25) ? lane : 24;
            const float* as = att_sm + s * 632;
            u64t ap[12];
            #pragma unroll
            for (int i = 0; i < 12; i++)
                ap[i] = pk2(as[(2 * i) * 25 + u], as[(2 * i + 1) * 25 + u]);
            float a24 = as[600 + u];

            #pragma unroll
            for (int cc = 0; cc < 4; cc++) {
                int c = wrp * 4 + cc;
                #pragma unroll
                for (int dt = 0; dt < TC3; dt++) {
                    const float* xr = x_sm + c * K3_XSTR + dt * K3_XPAD;
                    u64t acc2 = 0ULL;
                    #pragma unroll
                    for (int m = 0; m < 6; m++) {
                        ulonglong2 xx = *(const ulonglong2*)(xr + 4 * m);
                        fma2(acc2, xx.x, ap[2 * m]);
                        fma2(acc2, xx.y, ap[2 * m + 1]);
                    }
                    float2 f = up2(acc2);
                    float res = fmaf(xr[24], a24, f.x + f.y);
                    if (lane < 25)
                        y_sm[c * 128 + dt * 25 + lane] = res;
                }
            }
        }
        __syncthreads();

        // Phase Z: z[o][j] += sum_k wd[s,o,k] * y[k][j]   (K = 64)
        #pragma unroll 2
        for (int k = 0; k < 64; k++) {
            const float* wp = w_sm + k * 64 + o0;
            ulonglong2 wA = *(const ulonglong2*)(wp);      // pairs (o0,o0+1),(o0+2,o0+3)
            ulonglong2 wB = *(const ulonglong2*)(wp + 4);  // pairs (o0+4..7)
            float yv0 = y_sm[k * 128 + j0];
            float yv1 = y_sm[k * 128 + j0 + 32];
            u64t yq0 = pk2(yv0, yv0), yq1 = pk2(yv1, yv1);
            fma2(zacc[0], wA.x, yq0); fma2(zacc[1], wA.y, yq0);
            fma2(zacc[2], wB.x, yq0); fma2(zacc[3], wB.y, yq0);
            fma2(zacc[4], wA.x, yq1); fma2(zacc[5], wA.y, yq1);
            fma2(zacc[6], wB.x, yq1); fma2(zacc[7], wB.y, yq1);
        }
    }

    // Epilogue: BN + residual + ReLU
    float* og = out + (size_t)n * 64 * 7500 + (size_t)t0 * 25;
    #pragma unroll
    for (int q = 0; q < 2; q++) {
        int j = j0 + 32 * q;
        if (j < 125) {
            int dt = j / 25, u = j % 25;
            int xoff = dt * K3_XPAD + u;
            #pragma unroll
            for (int p = 0; p < 4; p++) {
                int oa = o0 + 2 * p, ob = oa + 1;
                float2 z = up2(zacc[q * 4 + p]);
                float ra = fmaf(z.x, sc_sm[oa], sh_sm[oa]) + x_sm[oa * K3_XSTR + xoff];
                float rb = fmaf(z.y, sc_sm[ob], sh_sm[ob]) + x_sm[ob * K3_XSTR + xoff];
                og[(size_t)oa * 7500 + j] = fmaxf(ra, 0.f);
                og[(size_t)ob * 7500 + j] = fmaxf(rb, 0.f);
            }
        }
    }
}

// ============================================================================
extern "C" void kernel_launch(void* const* d_in, const int* in_sizes, int n_in,
                              void* d_out, int out_size)
{
    const float* x   = (const float*)d_in[0];
    const float* A   = (const float*)d_in[1];
    const float* PA  = (const float*)d_in[2];
    const float* wa  = (const float*)d_in[3];
    const float* ba  = (const float*)d_in[4];
    const float* wb  = (const float*)d_in[5];
    const float* bb  = (const float*)d_in[6];
    const float* wd  = (const float*)d_in[7];
    const float* bd  = (const float*)d_in[8];
    const float* gma = (const float*)d_in[9];
    const float* bta = (const float*)d_in[10];
    const float* mu  = (const float*)d_in[11];
    const float* var = (const float*)d_in[12];
    float* out = (float*)d_out;

    cudaFuncSetAttribute(k1_scores, cudaFuncAttributeMaxDynamicSharedMemorySize, K1_SMEM);
    cudaFuncSetAttribute(k3_fused,  cudaFuncAttributeMaxDynamicSharedMemorySize, K3_SMEM);

    k1_scores<<<dim3(NB, NCH1), 512, K1_SMEM>>>(x, wa, ba, wb, bb);
    k2_softmax<<<dim3(NB, SS), 256>>>(A, PA);
    k3_fused<<<dim3(NB, NCH3), 512, K3_SMEM>>>(x, wd, bd, gma, bta, mu, var, out);
}

// round 6
// speedup vs baseline: 1.6245x; 1.1278x over previous
#include <cuda_runtime.h>
#include <math.h>

// Problem dims (fixed)
#define NB 64
#define TT 300
#define VV 25
#define SS 3

#define TC1 5
#define NCH1 (TT / TC1)          // 60 chunks for k1
#define TC3 5
#define NCH3 (TT / TC3)          // 60 chunks for k3

// Scratch (no allocations allowed)
__device__ float g_part[(size_t)NCH1 * NB * SS * VV * VV];  // 28.8 MB
__device__ float g_att[(size_t)NB * SS * VV * VV];          // 480 KB

// ---- packed f32x2 helpers (PTX-only; ptxas never auto-fuses FFMA2) --------
typedef unsigned long long u64t;
__device__ __forceinline__ u64t pk2(float a, float b) {
    u64t d; asm("mov.b64 %0,{%1,%2};" : "=l"(d) : "f"(a), "f"(b)); return d;
}
__device__ __forceinline__ void fma2(u64t& d, u64t a, u64t b) {
    asm("fma.rn.f32x2 %0,%1,%2,%0;" : "+l"(d) : "l"(a), "l"(b));
}
__device__ __forceinline__ float2 up2(u64t d) {
    float lo, hi; asm("mov.b64 {%0,%1},%2;" : "=f"(lo), "=f"(hi) : "l"(d));
    return make_float2(lo, hi);
}

// ============================================================================
// Kernel 1: fused conv_a + conv_b + partial score accumulation.
// 512 threads, TC1=5 frames/block, smem 104 KB -> 2 CTAs/SM.
// Phase 1: 8 row-groups(12) x 2 col-halves(64). Weights k-contiguous per
// group -> 3 broadcast LDS.128 per k give all 6 row-pairs; x 1 LDS.64.
// ============================================================================
#define K1_XS 128   // x / ab column stride (125 used)
#define K1_NF (64 * K1_XS + 96 * K1_XS + 8 * 64 * 12)   // 26624 floats
#define K1_SMEM (K1_NF * 4)                              // 106496 B

__global__ __launch_bounds__(512, 2)
void k1_scores(const float* __restrict__ x, const float* __restrict__ wa,
               const float* __restrict__ ba, const float* __restrict__ wb,
               const float* __restrict__ bb)
{
    const int n = blockIdx.x, ch = blockIdx.y, t0 = ch * TC1;
    const int tid = threadIdx.x, lane = tid & 31, wrp = tid >> 5;  // 16 warps

    extern __shared__ float sm[];
    float* x_sm  = sm;                       // [64][128]
    float* ab_sm = x_sm + 64 * K1_XS;        // [96][128] rows 0..47 a, 48..95 b
    float* w_sm  = ab_sm + 96 * K1_XS;       // [g][k][12] : base (g*64+k)*12

    // weights: w_sm[(g*64+k)*12 + r] = stacked[row = g*12+r][k]
    for (int i = tid; i < 8 * 64 * 12; i += 512) {
        int g = i / 768, rem = i % 768, k = rem / 12, r = rem % 12;
        int row = g * 12 + r;
        w_sm[i] = (row < 48) ? wa[row * 64 + k] : wb[(row - 48) * 64 + k];
    }
    const float* xg = x + (size_t)n * 64 * 7500 + (size_t)t0 * 25;
    for (int i = tid; i < 64 * K1_XS; i += 512) {
        int c = i >> 7, j = i & 127;
        x_sm[i] = (j < 125) ? xg[(size_t)c * 7500 + j] : 0.f;
    }
    __syncthreads();

    // Phase 1: 96 rows x 128 cols, K=64.
    {
        const int g = wrp >> 1;           // row-group, rows g*12..g*12+11
        const int half = wrp & 1;
        const int c0 = half * 64 + 2 * lane;
        const int r0 = g * 12;

        u64t acc[6][2];
        #pragma unroll
        for (int p = 0; p < 6; p++) {
            int ra = r0 + 2 * p, rb = ra + 1;
            float bA = (ra < 48) ? ba[ra] : bb[ra - 48];
            float bB = (rb < 48) ? ba[rb] : bb[rb - 48];
            u64t bi = pk2(bA, bB);
            acc[p][0] = bi; acc[p][1] = bi;
        }

        const ulonglong2* wp2 = (const ulonglong2*)(w_sm + g * 768);
        #pragma unroll 4
        for (int k = 0; k < 64; k++) {
            ulonglong2 wA = wp2[k * 3];       // pairs rows (0,1),(2,3)
            ulonglong2 wB = wp2[k * 3 + 1];   // (4,5),(6,7)
            ulonglong2 wC = wp2[k * 3 + 2];   // (8,9),(10,11)
            float2 xv = *(const float2*)(x_sm + k * K1_XS + c0);
            u64t xq0 = pk2(xv.x, xv.x), xq1 = pk2(xv.y, xv.y);
            fma2(acc[0][0], wA.x, xq0);  fma2(acc[0][1], wA.x, xq1);
            fma2(acc[1][0], wA.y, xq0);  fma2(acc[1][1], wA.y, xq1);
            fma2(acc[2][0], wB.x, xq0);  fma2(acc[2][1], wB.x, xq1);
            fma2(acc[3][0], wB.y, xq0);  fma2(acc[3][1], wB.y, xq1);
            fma2(acc[4][0], wC.x, xq0);  fma2(acc[4][1], wC.x, xq1);
            fma2(acc[5][0], wC.y, xq0);  fma2(acc[5][1], wC.y, xq1);
        }

        #pragma unroll
        for (int p = 0; p < 6; p++) {
            float2 f0 = up2(acc[p][0]);   // col c0  : {row ra, row rb}
            float2 f1 = up2(acc[p][1]);   // col c0+1
            int ra = r0 + 2 * p;
            *(float2*)(ab_sm + ra * K1_XS + c0)       = make_float2(f0.x, f1.x);
            *(float2*)(ab_sm + (ra + 1) * K1_XS + c0) = make_float2(f0.y, f1.y);
        }
    }
    __syncthreads();

    // Phase 2: partial scores over (k<16, dt<5). 15 tasks (s, v-strip of 5).
    const float inv = 1.0f / 4800.0f;
    for (int task = wrp; task < SS * 5; task += 16) {
        int s = task / 5, v0 = (task % 5) * 5;
        const float* arow0 = ab_sm + (s * 16) * K1_XS;
        const float* brow0 = ab_sm + (48 + s * 16) * K1_XS;
        float acc[5] = {0.f, 0.f, 0.f, 0.f, 0.f};
        for (int kk = 0; kk < 16; kk++) {
            const float* ar = arow0 + kk * K1_XS;
            const float* br = brow0 + kk * K1_XS;
            #pragma unroll
            for (int dt = 0; dt < TC1; dt++) {
                float bv = br[dt * 25 + lane];
                #pragma unroll
                for (int i = 0; i < 5; i++)
                    acc[i] = fmaf(ar[dt * 25 + v0 + i], bv, acc[i]);
            }
        }
        if (lane < 25) {
            float* dst = g_part + (((size_t)ch * NB + n) * SS + s) * 625;
            #pragma unroll
            for (int i = 0; i < 5; i++)
                dst[(v0 + i) * 25 + lane] = acc[i] * inv;
        }
    }
}

// ============================================================================
// Kernel 2: reduce chunk partials, softmax over v, add A+PA -> g_att
// ============================================================================
__global__ void k2_softmax(const float* __restrict__ A, const float* __restrict__ PA)
{
    const int n = blockIdx.x, s = blockIdx.y;
    __shared__ float sc[625];
    const int tid = threadIdx.x;

    for (int i = tid; i < 625; i += 256) {
        float acc = 0.f;
        for (int ch = 0; ch < NCH1; ch++)
            acc += g_part[(((size_t)ch * NB + n) * SS + s) * 625 + i];
        sc[i] = acc;
    }
    __syncthreads();

    if (tid < 25) {
        const int u = tid;
        float mx = -1e30f;
        #pragma unroll
        for (int v = 0; v < 25; v++) mx = fmaxf(mx, sc[v * 25 + u]);
        float e[25], sum = 0.f;
        #pragma unroll
        for (int v = 0; v < 25; v++) { e[v] = expf(sc[v * 25 + u] - mx); sum += e[v]; }
        const float rs = 1.f / sum;
        #pragma unroll
        for (int v = 0; v < 25; v++) {
            int idx = s * 625 + v * 25 + u;
            g_att[((size_t)n * SS + s) * 625 + v * 25 + u] = e[v] * rs + A[idx] + PA[idx];
        }
    }
}

// ============================================================================
// Kernel 3: subset-sequential fused y = x@att_s -> z += wd_s@y, then
// BN + residual + ReLU. 512 threads, smem ~91 KB -> 2 CTAs/SM.
// Phase Y: dual fma2 chains (ILP 2). Phase Z: o-pair packing.
// ============================================================================
#define K3_XPAD 28                         // v padded 25 -> 28
#define K3_XSTR (TC3 * K3_XPAD)            // 140 floats per channel row
#define K3_NF (64 * K3_XSTR + 64 * 128 + 64 * 64 + 3 * 632 + 128)  // 23272 floats
#define K3_SMEM (K3_NF * 4)                                         // 93088 B

__global__ __launch_bounds__(512, 2)
void k3_fused(const float* __restrict__ x, const float* __restrict__ wd,
              const float* __restrict__ bd,
              const float* __restrict__ gma, const float* __restrict__ bta,
              const float* __restrict__ mu,  const float* __restrict__ var,
              float* __restrict__ out)
{
    const int n = blockIdx.x, ch = blockIdx.y, t0 = ch * TC3;
    const int tid = threadIdx.x, lane = tid & 31, wrp = tid >> 5;

    extern __shared__ float sm[];
    float* x_sm   = sm;                          // [64][140]  (dt*28+v layout)
    float* y_sm   = x_sm + 64 * K3_XSTR;         // [64][128]  one subset
    float* w_sm   = y_sm + 64 * 128;             // [64][64]   w_sm[k*64+o]
    float* att_sm = w_sm + 64 * 64;              // [3][632]
    float* sc_sm  = att_sm + 3 * 632;            // [64]
    float* sh_sm  = sc_sm + 64;                  // [64]

    const float* xg = x + (size_t)n * 64 * 7500 + (size_t)t0 * 25;
    for (int i = tid; i < 64 * 125; i += 512) {
        int c = i / 125, j = i % 125, dt = j / 25, v = j % 25;
        x_sm[c * K3_XSTR + dt * K3_XPAD + v] = xg[(size_t)c * 7500 + j];
    }
    for (int i = tid; i < SS * 625; i += 512) {
        int s = i / 625, r = i % 625;
        att_sm[s * 632 + r] = g_att[((size_t)n * SS + s) * 625 + r];
    }
    if (tid < 64) {
        float scl = gma[tid] * rsqrtf(var[tid] + 1e-5f);
        float bsum = bd[tid] + bd[64 + tid] + bd[128 + tid];
        sc_sm[tid] = scl;
        sh_sm[tid] = (bsum - mu[tid]) * scl + bta[tid];
    }

    const int o0 = (wrp >> 1) * 8;
    const int half = wrp & 1;
    const int j0 = lane + 64 * half;
    u64t zacc[8];
    #pragma unroll
    for (int r = 0; r < 8; r++) zacc[r] = 0ULL;

    for (int s = 0; s < SS; s++) {
        __syncthreads();   // y_sm/w_sm free (also covers initial loads on s=0)

        // this subset's conv_d weights transposed via LDG.128:
        // wd[s][o][k] k-contiguous -> w_sm[k*64+o]
        {
            const float4* wdv = (const float4*)(wd + (size_t)s * 4096);
            for (int i = tid; i < 1024; i += 512) {
                float4 v = wdv[i];
                int o = i >> 4, k0 = (i & 15) * 4;
                w_sm[(k0    ) * 64 + o] = v.x;
                w_sm[(k0 + 1) * 64 + o] = v.y;
                w_sm[(k0 + 2) * 64 + o] = v.z;
                w_sm[(k0 + 3) * 64 + o] = v.w;
            }
        }

        // Phase Y: y[c][dt*25+u] = sum_v x[c][dt][v] * att_s[v][u]
        {
            const int u = (lane < 25) ? lane : 24;
            const float* as = att_sm + s * 632;
            u64t ap[12];
            #pragma unroll
            for (int i = 0; i < 12; i++)
                ap[i] = pk2(as[(2 * i) * 25 + u], as[(2 * i + 1) * 25 + u]);
            float a24 = as[600 + u];

            #pragma unroll
            for (int cc = 0; cc < 4; cc++) {
                int c = wrp * 4 + cc;
                #pragma unroll
                for (int dt = 0; dt < TC3; dt++) {
                    const float* xr = x_sm + c * K3_XSTR + dt * K3_XPAD;
                    u64t acc2a = 0ULL, acc2b = 0ULL;   // dual chains (ILP 2)
                    #pragma unroll
                    for (int m = 0; m < 6; m += 2) {
                        ulonglong2 xx0 = *(const ulonglong2*)(xr + 4 * m);
                        ulonglong2 xx1 = *(const ulonglong2*)(xr + 4 * m + 4);
                        fma2(acc2a, xx0.x, ap[2 * m]);
                        fma2(acc2b, xx0.y, ap[2 * m + 1]);
                        fma2(acc2a, xx1.x, ap[2 * m + 2]);
                        fma2(acc2b, xx1.y, ap[2 * m + 3]);
                    }
                    float2 fa = up2(acc2a), fb = up2(acc2b);
                    float res = fmaf(xr[24], a24, (fa.x + fb.x) + (fa.y + fb.y));
                    if (lane < 25)
                        y_sm[c * 128 + dt * 25 + lane] = res;
                }
            }
        }
        __syncthreads();

        // Phase Z: z[o][j] += sum_k wd[s,o,k] * y[k][j]   (K = 64)
        #pragma unroll 2
        for (int k = 0; k < 64; k++) {
            const float* wp = w_sm + k * 64 + o0;
            ulonglong2 wA = *(const ulonglong2*)(wp);      // o-pairs (0,1),(2,3)
            ulonglong2 wB = *(const ulonglong2*)(wp + 4);  // (4,5),(6,7)
            float yv0 = y_sm[k * 128 + j0];
            float yv1 = y_sm[k * 128 + j0 + 32];
            u64t yq0 = pk2(yv0, yv0), yq1 = pk2(yv1, yv1);
            fma2(zacc[0], wA.x, yq0); fma2(zacc[1], wA.y, yq0);
            fma2(zacc[2], wB.x, yq0); fma2(zacc[3], wB.y, yq0);
            fma2(zacc[4], wA.x, yq1); fma2(zacc[5], wA.y, yq1);
            fma2(zacc[6], wB.x, yq1); fma2(zacc[7], wB.y, yq1);
        }
    }

    // Epilogue: BN + residual + ReLU
    float* og = out + (size_t)n * 64 * 7500 + (size_t)t0 * 25;
    #pragma unroll
    for (int q = 0; q < 2; q++) {
        int j = j0 + 32 * q;
        if (j < 125) {
            int dt = j / 25, u = j % 25;
            int xoff = dt * K3_XPAD + u;
            #pragma unroll
            for (int p = 0; p < 4; p++) {
                int oa = o0 + 2 * p, ob = oa + 1;
                float2 z = up2(zacc[q * 4 + p]);
                float ra = fmaf(z.x, sc_sm[oa], sh_sm[oa]) + x_sm[oa * K3_XSTR + xoff];
                float rb = fmaf(z.y, sc_sm[ob], sh_sm[ob]) + x_sm[ob * K3_XSTR + xoff];
                og[(size_t)oa * 7500 + j] = fmaxf(ra, 0.f);
                og[(size_t)ob * 7500 + j] = fmaxf(rb, 0.f);
            }
        }
    }
}

// ============================================================================
extern "C" void kernel_launch(void* const* d_in, const int* in_sizes, int n_in,
                              void* d_out, int out_size)
{
    const float* x   = (const float*)d_in[0];
    const float* A   = (const float*)d_in[1];
    const float* PA  = (const float*)d_in[2];
    const float* wa  = (const float*)d_in[3];
    const float* ba  = (const float*)d_in[4];
    const float* wb  = (const float*)d_in[5];
    const float* bb  = (const float*)d_in[6];
    const float* wd  = (const float*)d_in[7];
    const float* bd  = (const float*)d_in[8];
    const float* gma = (const float*)d_in[9];
    const float* bta = (const float*)d_in[10];
    const float* mu  = (const float*)d_in[11];
    const float* var = (const float*)d_in[12];
    float* out = (float*)d_out;

    cudaFuncSetAttribute(k1_scores, cudaFuncAttributeMaxDynamicSharedMemorySize, K1_SMEM);
    cudaFuncSetAttribute(k3_fused,  cudaFuncAttributeMaxDynamicSharedMemorySize, K3_SMEM);

    k1_scores<<<dim3(NB, NCH1), 512, K1_SMEM>>>(x, wa, ba, wb, bb);
    k2_softmax<<<dim3(NB, SS), 256>>>(A, PA);
    k3_fused<<<dim3(NB, NCH3), 512, K3_SMEM>>>(x, wd, bd, gma, bta, mu, var, out);
}

// round 8
// speedup vs baseline: 1.8085x; 1.1133x over previous
#include <cuda_runtime.h>
#include <cuda_bf16.h>
#include <cstdint>
#include <math.h>

typedef unsigned int u32;

// Problem dims (fixed)
#define NB 64
#define TT 300
#define VV 25
#define SS 3

#define TC1 5
#define NCH1 (TT / TC1)          // 60 chunks for k1
#define TC3 5
#define NCH3 (TT / TC3)          // 60 chunks for k3

// Scratch (no allocations allowed)
__device__ float g_part[(size_t)NCH1 * NB * SS * VV * VV];  // 28.8 MB
__device__ float g_att[(size_t)NB * SS * VV * VV];          // 480 KB

// ---- packed f32x2 helpers (PTX-only) --------------------------------------
typedef unsigned long long u64t;
__device__ __forceinline__ u64t pk2(float a, float b) {
    u64t d; asm("mov.b64 %0,{%1,%2};" : "=l"(d) : "f"(a), "f"(b)); return d;
}
__device__ __forceinline__ void fma2(u64t& d, u64t a, u64t b) {
    asm("fma.rn.f32x2 %0,%1,%2,%0;" : "+l"(d) : "l"(a), "l"(b));
}
__device__ __forceinline__ float2 up2(u64t d) {
    float lo, hi; asm("mov.b64 {%0,%1},%2;" : "=f"(lo), "=f"(hi) : "l"(d));
    return make_float2(lo, hi);
}

// ---- bf16 mma helpers ------------------------------------------------------
__device__ __forceinline__ void mma_bf16(float& d0, float& d1, float& d2, float& d3,
                                         u32 a0, u32 a1, u32 a2, u32 a3,
                                         u32 b0, u32 b1) {
    asm("mma.sync.aligned.m16n8k16.row.col.f32.bf16.bf16.f32 "
        "{%0,%1,%2,%3},{%4,%5,%6,%7},{%8,%9},{%0,%1,%2,%3};"
        : "+f"(d0), "+f"(d1), "+f"(d2), "+f"(d3)
        : "r"(a0), "r"(a1), "r"(a2), "r"(a3), "r"(b0), "r"(b1));
}
__device__ __forceinline__ u32 ldb2(const __nv_bfloat16* p) {
    return *reinterpret_cast<const u32*>(p);
}

// ============================================================================
// Kernel 1: fused conv_a + conv_b + partial score accumulation. (unchanged)
// ============================================================================
#define K1_XS 128
#define K1_NF (64 * K1_XS + 96 * K1_XS + 8 * 64 * 12)
#define K1_SMEM (K1_NF * 4)

__global__ __launch_bounds__(512, 2)
void k1_scores(const float* __restrict__ x, const float* __restrict__ wa,
               const float* __restrict__ ba, const float* __restrict__ wb,
               const float* __restrict__ bb)
{
    const int n = blockIdx.x, ch = blockIdx.y, t0 = ch * TC1;
    const int tid = threadIdx.x, lane = tid & 31, wrp = tid >> 5;

    extern __shared__ float sm[];
    float* x_sm  = sm;                       // [64][128]
    float* ab_sm = x_sm + 64 * K1_XS;        // [96][128]
    float* w_sm  = ab_sm + 96 * K1_XS;       // [g][k][12]

    for (int i = tid; i < 8 * 64 * 12; i += 512) {
        int g = i / 768, rem = i % 768, k = rem / 12, r = rem % 12;
        int row = g * 12 + r;
        w_sm[i] = (row < 48) ? wa[row * 64 + k] : wb[(row - 48) * 64 + k];
    }
    const float* xg = x + (size_t)n * 64 * 7500 + (size_t)t0 * 25;
    for (int i = tid; i < 64 * K1_XS; i += 512) {
        int c = i >> 7, j = i & 127;
        x_sm[i] = (j < 125) ? xg[(size_t)c * 7500 + j] : 0.f;
    }
    __syncthreads();

    {
        const int g = wrp >> 1;
        const int half = wrp & 1;
        const int c0 = half * 64 + 2 * lane;
        const int r0 = g * 12;

        u64t acc[6][2];
        #pragma unroll
        for (int p = 0; p < 6; p++) {
            int ra = r0 + 2 * p, rb = ra + 1;
            float bA = (ra < 48) ? ba[ra] : bb[ra - 48];
            float bB = (rb < 48) ? ba[rb] : bb[rb - 48];
            u64t bi = pk2(bA, bB);
            acc[p][0] = bi; acc[p][1] = bi;
        }

        const ulonglong2* wp2 = (const ulonglong2*)(w_sm + g * 768);
        #pragma unroll 4
        for (int k = 0; k < 64; k++) {
            ulonglong2 wA = wp2[k * 3];
            ulonglong2 wB = wp2[k * 3 + 1];
            ulonglong2 wC = wp2[k * 3 + 2];
            float2 xv = *(const float2*)(x_sm + k * K1_XS + c0);
            u64t xq0 = pk2(xv.x, xv.x), xq1 = pk2(xv.y, xv.y);
            fma2(acc[0][0], wA.x, xq0);  fma2(acc[0][1], wA.x, xq1);
            fma2(acc[1][0], wA.y, xq0);  fma2(acc[1][1], wA.y, xq1);
            fma2(acc[2][0], wB.x, xq0);  fma2(acc[2][1], wB.x, xq1);
            fma2(acc[3][0], wB.y, xq0);  fma2(acc[3][1], wB.y, xq1);
            fma2(acc[4][0], wC.x, xq0);  fma2(acc[4][1], wC.x, xq1);
            fma2(acc[5][0], wC.y, xq0);  fma2(acc[5][1], wC.y, xq1);
        }

        #pragma unroll
        for (int p = 0; p < 6; p++) {
            float2 f0 = up2(acc[p][0]);
            float2 f1 = up2(acc[p][1]);
            int ra = r0 + 2 * p;
            *(float2*)(ab_sm + ra * K1_XS + c0)       = make_float2(f0.x, f1.x);
            *(float2*)(ab_sm + (ra + 1) * K1_XS + c0) = make_float2(f0.y, f1.y);
        }
    }
    __syncthreads();

    const float inv = 1.0f / 4800.0f;
    for (int task = wrp; task < SS * 5; task += 16) {
        int s = task / 5, v0 = (task % 5) * 5;
        const float* arow0 = ab_sm + (s * 16) * K1_XS;
        const float* brow0 = ab_sm + (48 + s * 16) * K1_XS;
        float acc[5] = {0.f, 0.f, 0.f, 0.f, 0.f};
        for (int kk = 0; kk < 16; kk++) {
            const float* ar = arow0 + kk * K1_XS;
            const float* br = brow0 + kk * K1_XS;
            #pragma unroll
            for (int dt = 0; dt < TC1; dt++) {
                float bv = br[dt * 25 + lane];
                #pragma unroll
                for (int i = 0; i < 5; i++)
                    acc[i] = fmaf(ar[dt * 25 + v0 + i], bv, acc[i]);
            }
        }
        if (lane < 25) {
            float* dst = g_part + (((size_t)ch * NB + n) * SS + s) * 625;
            #pragma unroll
            for (int i = 0; i < 5; i++)
                dst[(v0 + i) * 25 + lane] = acc[i] * inv;
        }
    }
}

// ============================================================================
// Kernel 2: reduce chunk partials, softmax over v, add A+PA -> g_att
// ============================================================================
__global__ void k2_softmax(const float* __restrict__ A, const float* __restrict__ PA)
{
    const int n = blockIdx.x, s = blockIdx.y;
    __shared__ float sc[625];
    const int tid = threadIdx.x;

    for (int i = tid; i < 625; i += 256) {
        float acc = 0.f;
        for (int ch = 0; ch < NCH1; ch++)
            acc += g_part[(((size_t)ch * NB + n) * SS + s) * 625 + i];
        sc[i] = acc;
    }
    __syncthreads();

    if (tid < 25) {
        const int u = tid;
        float mx = -1e30f;
        #pragma unroll
        for (int v = 0; v < 25; v++) mx = fmaxf(mx, sc[v * 25 + u]);
        float e[25], sum = 0.f;
        #pragma unroll
        for (int v = 0; v < 25; v++) { e[v] = expf(sc[v * 25 + u] - mx); sum += e[v]; }
        const float rs = 1.f / sum;
        #pragma unroll
        for (int v = 0; v < 25; v++) {
            int idx = s * 625 + v * 25 + u;
            g_att[((size_t)n * SS + s) * 625 + v * 25 + u] = e[v] * rs + A[idx] + PA[idx];
        }
    }
}

// ============================================================================
// Kernel 3: phase Y scalar (f32x2), phase Z on TENSOR CORES.
// z = sum_s wd_s @ y_s via mma.sync m16n8k16 bf16 with 2-term bf16 split
// (wh*yh + wh*yl + wl*yh). y stored transposed [j][k] hi/lo bf16, 72-pad
// (conflict-free fragment loads). D frags accumulate across subsets; epilogue
// BN + residual + ReLU from fragments.
// ============================================================================
#define K3_XPAD 28
#define K3_XSTR (TC3 * K3_XPAD)            // 140
#define K3_OFF_X   0
#define K3_OFF_ATT (64 * K3_XSTR)          // 8960
#define K3_OFF_SC  (K3_OFF_ATT + 3 * 632)  // 10856
#define K3_OFF_SH  (K3_OFF_SC + 64)        // 10920
#define K3_OFF_WH  (K3_OFF_SH + 64)        // 10984 (bf16 region start, 4B aligned)
#define K3_OFF_WL  (K3_OFF_WH + 2304)      // each w: 64*72 bf16 = 2304 floats
#define K3_OFF_YH  (K3_OFF_WL + 2304)
#define K3_OFF_YL  (K3_OFF_YH + 4608)      // each y: 128*72 bf16 = 4608 floats
#define K3_NF      (K3_OFF_YL + 4608)      // 24808 floats
#define K3_SMEM    (K3_NF * 4)             // 99232 B

__global__ __launch_bounds__(512, 2)
void k3_fused(const float* __restrict__ x, const float* __restrict__ wd,
              const float* __restrict__ bd,
              const float* __restrict__ gma, const float* __restrict__ bta,
              const float* __restrict__ mu,  const float* __restrict__ var,
              float* __restrict__ out)
{
    const int n = blockIdx.x, ch = blockIdx.y, t0 = ch * TC3;
    const int tid = threadIdx.x, lane = tid & 31, wrp = tid >> 5;
    const int quad = lane >> 2, t4 = lane & 3;

    extern __shared__ float sm[];
    float* x_sm   = sm + K3_OFF_X;              // [64][140]
    float* att_sm = sm + K3_OFF_ATT;            // [3][632]
    float* sc_sm  = sm + K3_OFF_SC;             // [64]
    float* sh_sm  = sm + K3_OFF_SH;             // [64]
    __nv_bfloat16* w_hi = (__nv_bfloat16*)(sm + K3_OFF_WH);  // [64][72]
    __nv_bfloat16* w_lo = (__nv_bfloat16*)(sm + K3_OFF_WL);
    __nv_bfloat16* y_hi = (__nv_bfloat16*)(sm + K3_OFF_YH);  // [128][72]
    __nv_bfloat16* y_lo = (__nv_bfloat16*)(sm + K3_OFF_YL);

    // ---- initial loads -----------------------------------------------------
    const float* xg = x + (size_t)n * 64 * 7500 + (size_t)t0 * 25;
    for (int i = tid; i < 64 * 125; i += 512) {
        int c = i / 125, j = i % 125, dt = j / 25, v = j % 25;
        x_sm[c * K3_XSTR + dt * K3_XPAD + v] = xg[(size_t)c * 7500 + j];
    }
    for (int i = tid; i < SS * 625; i += 512) {
        int s = i / 625, r = i % 625;
        att_sm[s * 632 + r] = g_att[((size_t)n * SS + s) * 625 + r];
    }
    if (tid < 64) {
        float scl = gma[tid] * rsqrtf(var[tid] + 1e-5f);
        float bsum = bd[tid] + bd[64 + tid] + bd[128 + tid];
        sc_sm[tid] = scl;
        sh_sm[tid] = (bsum - mu[tid]) * scl + bta[tid];
    }
    // zero the y rows j=125..127 (read by mma, results discarded; avoid NaN)
    if (tid < 3 * 72) {
        y_hi[125 * 72 + tid] = __float2bfloat16_rn(0.f);
        y_lo[125 * 72 + tid] = __float2bfloat16_rn(0.f);
    }

    // warp tile assignment for phase Z
    const int o0 = (wrp >> 2) * 16;   // 4 o-tiles of 16
    const int jg = wrp & 3;           // j-group of 32 (4 n8 tiles)
    float d[4][4];
    #pragma unroll
    for (int f = 0; f < 4; f++)
        #pragma unroll
        for (int q = 0; q < 4; q++) d[f][q] = 0.f;

    for (int s = 0; s < SS; s++) {
        __syncthreads();   // prev mma done reading w/y; covers init loads on s=0

        // load + split this subset's conv_d weights: w_hi/lo[o][k]
        for (int i = tid; i < 4096; i += 512) {
            int o = i >> 6, k = i & 63;
            float v = wd[(size_t)s * 4096 + i];
            __nv_bfloat16 h = __float2bfloat16_rn(v);
            w_hi[o * 72 + k] = h;
            w_lo[o * 72 + k] = __float2bfloat16_rn(v - __bfloat162float(h));
        }

        // Phase Y: y[c][j=dt*25+u] = sum_v x[c][dt][v] * att_s[v][u]
        {
            const int u = (lane < 25) ? lane : 24;
            const float* as = att_sm + s * 632;
            u64t ap[12];
            #pragma unroll
            for (int i = 0; i < 12; i++)
                ap[i] = pk2(as[(2 * i) * 25 + u], as[(2 * i + 1) * 25 + u]);
            float a24 = as[600 + u];

            #pragma unroll
            for (int cc = 0; cc < 4; cc++) {
                int c = wrp * 4 + cc;
                #pragma unroll
                for (int dt = 0; dt < TC3; dt++) {
                    const float* xr = x_sm + c * K3_XSTR + dt * K3_XPAD;
                    u64t acc2a = 0ULL, acc2b = 0ULL;
                    #pragma unroll
                    for (int m = 0; m < 6; m += 2) {
                        ulonglong2 xx0 = *(const ulonglong2*)(xr + 4 * m);
                        ulonglong2 xx1 = *(const ulonglong2*)(xr + 4 * m + 4);
                        fma2(acc2a, xx0.x, ap[2 * m]);
                        fma2(acc2b, xx0.y, ap[2 * m + 1]);
                        fma2(acc2a, xx1.x, ap[2 * m + 2]);
                        fma2(acc2b, xx1.y, ap[2 * m + 3]);
                    }
                    float2 fa = up2(acc2a), fb = up2(acc2b);
                    float res = fmaf(xr[24], a24, (fa.x + fb.x) + (fa.y + fb.y));
                    if (lane < 25) {
                        int j = dt * 25 + lane;
                        __nv_bfloat16 h = __float2bfloat16_rn(res);
                        y_hi[j * 72 + c] = h;
                        y_lo[j * 72 + c] = __float2bfloat16_rn(res - __bfloat162float(h));
                    }
                }
            }
        }
        __syncthreads();

        // Phase Z: tensor-core accumulation, K = 64 for this subset
        #pragma unroll
        for (int k0 = 0; k0 < 64; k0 += 16) {
            const int ar0 = (o0 + quad) * 72 + k0 + 2 * t4;
            const int ar1 = (o0 + quad + 8) * 72 + k0 + 2 * t4;
            u32 ah0 = ldb2(w_hi + ar0),     ah1 = ldb2(w_hi + ar1);
            u32 ah2 = ldb2(w_hi + ar0 + 8), ah3 = ldb2(w_hi + ar1 + 8);
            u32 al0 = ldb2(w_lo + ar0),     al1 = ldb2(w_lo + ar1);
            u32 al2 = ldb2(w_lo + ar0 + 8), al3 = ldb2(w_lo + ar1 + 8);
            #pragma unroll
            for (int f = 0; f < 4; f++) {
                int j = jg * 32 + f * 8 + quad;
                int br = j * 72 + k0 + 2 * t4;
                u32 bh0 = ldb2(y_hi + br), bh1 = ldb2(y_hi + br + 8);
                u32 bl0 = ldb2(y_lo + br), bl1 = ldb2(y_lo + br + 8);
                mma_bf16(d[f][0], d[f][1], d[f][2], d[f][3],
                         ah0, ah1, ah2, ah3, bh0, bh1);
                mma_bf16(d[f][0], d[f][1], d[f][2], d[f][3],
                         ah0, ah1, ah2, ah3, bl0, bl1);
                mma_bf16(d[f][0], d[f][1], d[f][2], d[f][3],
                         al0, al1, al2, al3, bh0, bh1);
            }
        }
    }

    // ---- epilogue: BN + residual + ReLU from D fragments -------------------
    float* og = out + (size_t)n * 64 * 7500 + (size_t)t0 * 25;
    #pragma unroll
    for (int f = 0; f < 4; f++) {
        int jb = jg * 32 + f * 8 + 2 * t4;
        #pragma unroll
        for (int h = 0; h < 2; h++) {
            int o = o0 + quad + 8 * h;
            float scl = sc_sm[o], shf = sh_sm[o];
            #pragma unroll
            for (int cc = 0; cc < 2; cc++) {
                int j = jb + cc;
                if (j < 125) {
                    int dt = j / 25, u = j - dt * 25;
                    float r = fmaf(d[f][2 * h + cc], scl, shf)
                              + x_sm[o * K3_XSTR + dt * K3_XPAD + u];
                    og[(size_t)o * 7500 + j] = fmaxf(r, 0.f);
                }
            }
        }
    }
}

// ============================================================================
extern "C" void kernel_launch(void* const* d_in, const int* in_sizes, int n_in,
                              void* d_out, int out_size)
{
    const float* x   = (const float*)d_in[0];
    const float* A   = (const float*)d_in[1];
    const float* PA  = (const float*)d_in[2];
    const float* wa  = (const float*)d_in[3];
    const float* ba  = (const float*)d_in[4];
    const float* wb  = (const float*)d_in[5];
    const float* bb  = (const float*)d_in[6];
    const float* wd  = (const float*)d_in[7];
    const float* bd  = (const float*)d_in[8];
    const float* gma = (const float*)d_in[9];
    const float* bta = (const float*)d_in[10];
    const float* mu  = (const float*)d_in[11];
    const float* var = (const float*)d_in[12];
    float* out = (float*)d_out;

    cudaFuncSetAttribute(k1_scores, cudaFuncAttributeMaxDynamicSharedMemorySize, K1_SMEM);
    cudaFuncSetAttribute(k3_fused,  cudaFuncAttributeMaxDynamicSharedMemorySize, K3_SMEM);

    k1_scores<<<dim3(NB, NCH1), 512, K1_SMEM>>>(x, wa, ba, wb, bb);
    k2_softmax<<<dim3(NB, SS), 256>>>(A, PA);
    k3_fused<<<dim3(NB, NCH3), 512, K3_SMEM>>>(x, wd, bd, gma, bta, mu, var, out);
}

// round 9
// speedup vs baseline: 1.9860x; 1.0981x over previous
#include <cuda_runtime.h>
#include <cuda_bf16.h>
#include <cstdint>
#include <math.h>

typedef unsigned int u32;

// Problem dims (fixed)
#define NB 64
#define TT 300
#define VV 25
#define SS 3

#define TC1 5
#define NCH1 (TT / TC1)          // 60 chunks for k1
#define TC3 5
#define NCH3 (TT / TC3)          // 60 chunks for k3

// Scratch (no allocations allowed)
__device__ float g_part[(size_t)NCH1 * NB * SS * VV * VV];  // 28.8 MB
__device__ float g_att[(size_t)NB * SS * VV * VV];          // 480 KB

// ---- packed f32x2 helpers (PTX-only) --------------------------------------
typedef unsigned long long u64t;
__device__ __forceinline__ u64t pk2(float a, float b) {
    u64t d; asm("mov.b64 %0,{%1,%2};" : "=l"(d) : "f"(a), "f"(b)); return d;
}
__device__ __forceinline__ void fma2(u64t& d, u64t a, u64t b) {
    asm("fma.rn.f32x2 %0,%1,%2,%0;" : "+l"(d) : "l"(a), "l"(b));
}
__device__ __forceinline__ float2 up2(u64t d) {
    float lo, hi; asm("mov.b64 {%0,%1},%2;" : "=f"(lo), "=f"(hi) : "l"(d));
    return make_float2(lo, hi);
}

// ---- bf16 mma helpers ------------------------------------------------------
__device__ __forceinline__ void mma_bf16(float& d0, float& d1, float& d2, float& d3,
                                         u32 a0, u32 a1, u32 a2, u32 a3,
                                         u32 b0, u32 b1) {
    asm("mma.sync.aligned.m16n8k16.row.col.f32.bf16.bf16.f32 "
        "{%0,%1,%2,%3},{%4,%5,%6,%7},{%8,%9},{%0,%1,%2,%3};"
        : "+f"(d0), "+f"(d1), "+f"(d2), "+f"(d3)
        : "r"(a0), "r"(a1), "r"(a2), "r"(a3), "r"(b0), "r"(b1));
}
__device__ __forceinline__ u32 ldb2(const __nv_bfloat16* p) {
    return *reinterpret_cast<const u32*>(p);
}

// ============================================================================
// Kernel 1: conv_a/conv_b on TENSOR CORES (m16n8k16 bf16, w hi/lo split,
// x hi only), then scalar score accumulation from f32 ab_sm.
// ab = W[96x64] @ Xt[128x64]^T per block. smem 95.2 KB -> 2 CTAs/SM.
// ============================================================================
#define K1_ABS 128                        // ab col stride
#define K1_OFF_AB 0                       // 96*128 f32 = 12288 floats
#define K1_OFF_XT 12288                   // 128*72 bf16 = 4608 floats
#define K1_OFF_WH (12288 + 4608)          // 96*72 bf16 = 3456 floats
#define K1_OFF_WL (K1_OFF_WH + 3456)
#define K1_NF     (K1_OFF_WL + 3456)      // 23808 floats
#define K1_SMEM   (K1_NF * 4)             // 95232 B

__global__ __launch_bounds__(512, 2)
void k1_scores(const float* __restrict__ x, const float* __restrict__ wa,
               const float* __restrict__ ba, const float* __restrict__ wb,
               const float* __restrict__ bb)
{
    const int n = blockIdx.x, ch = blockIdx.y, t0 = ch * TC1;
    const int tid = threadIdx.x, lane = tid & 31, wrp = tid >> 5;
    const int quad = lane >> 2, t4 = lane & 3;

    extern __shared__ float sm[];
    float* ab_sm = sm + K1_OFF_AB;                           // [96][128] f32
    __nv_bfloat16* xt = (__nv_bfloat16*)(sm + K1_OFF_XT);    // [128][72] (x^T)
    __nv_bfloat16* w_hi = (__nv_bfloat16*)(sm + K1_OFF_WH);  // [96][72]
    __nv_bfloat16* w_lo = (__nv_bfloat16*)(sm + K1_OFF_WL);

    // stacked conv_a/conv_b weights, hi/lo split: row<48 -> wa, else wb
    for (int i = tid; i < 96 * 64; i += 512) {
        int row = i >> 6, k = i & 63;
        float v = (row < 48) ? wa[row * 64 + k] : wb[(row - 48) * 64 + k];
        __nv_bfloat16 h = __float2bfloat16_rn(v);
        w_hi[row * 72 + k] = h;
        w_lo[row * 72 + k] = __float2bfloat16_rn(v - __bfloat162float(h));
    }
    // x chunk transposed to [col j][k=c], bf16 hi; cols 125..127 zero
    const float* xg = x + (size_t)n * 64 * 7500 + (size_t)t0 * 25;
    for (int i = tid; i < 64 * 128; i += 512) {
        int c = i >> 7, j = i & 127;
        float v = (j < 125) ? xg[(size_t)c * 7500 + j] : 0.f;
        xt[j * 72 + c] = __float2bfloat16_rn(v);
    }
    __syncthreads();

    // Phase 1: mma. 48 jobs of m16 x n16; warp does jobs wrp, wrp+16, wrp+32.
    #pragma unroll
    for (int jj = 0; jj < 3; jj++) {
        const int job = wrp + 16 * jj;
        const int mi = job >> 3, nq = job & 7;
        const int r0 = mi * 16 + quad;

        float d[2][4];
        #pragma unroll
        for (int h = 0; h < 2; h++)
            #pragma unroll
            for (int q = 0; q < 4; q++) d[h][q] = 0.f;

        #pragma unroll
        for (int ks = 0; ks < 4; ks++) {
            const int ka = ks * 16 + 2 * t4;
            u32 ah0 = ldb2(w_hi + r0 * 72 + ka);
            u32 ah1 = ldb2(w_hi + (r0 + 8) * 72 + ka);
            u32 ah2 = ldb2(w_hi + r0 * 72 + ka + 8);
            u32 ah3 = ldb2(w_hi + (r0 + 8) * 72 + ka + 8);
            u32 al0 = ldb2(w_lo + r0 * 72 + ka);
            u32 al1 = ldb2(w_lo + (r0 + 8) * 72 + ka);
            u32 al2 = ldb2(w_lo + r0 * 72 + ka + 8);
            u32 al3 = ldb2(w_lo + (r0 + 8) * 72 + ka + 8);
            #pragma unroll
            for (int h = 0; h < 2; h++) {
                int jcol = nq * 16 + h * 8 + quad;
                u32 b0 = ldb2(xt + jcol * 72 + ka);
                u32 b1 = ldb2(xt + jcol * 72 + ka + 8);
                mma_bf16(d[h][0], d[h][1], d[h][2], d[h][3],
                         ah0, ah1, ah2, ah3, b0, b1);
                mma_bf16(d[h][0], d[h][1], d[h][2], d[h][3],
                         al0, al1, al2, al3, b0, b1);
            }
        }

        // bias + store to ab_sm (f32)
        const int ra = r0, rb = r0 + 8;
        const float biasA = (ra < 48) ? ba[ra] : bb[ra - 48];
        const float biasB = (rb < 48) ? ba[rb] : bb[rb - 48];
        #pragma unroll
        for (int h = 0; h < 2; h++) {
            int cb = nq * 16 + h * 8 + 2 * t4;
            *(float2*)(ab_sm + ra * K1_ABS + cb) =
                make_float2(d[h][0] + biasA, d[h][1] + biasA);
            *(float2*)(ab_sm + rb * K1_ABS + cb) =
                make_float2(d[h][2] + biasB, d[h][3] + biasB);
        }
    }
    __syncthreads();

    // Phase 2: partial scores over (k<16, dt<5). 15 tasks (s, v-strip of 5).
    const float inv = 1.0f / 4800.0f;
    for (int task = wrp; task < SS * 5; task += 16) {
        int s = task / 5, v0 = (task % 5) * 5;
        const float* arow0 = ab_sm + (s * 16) * K1_ABS;
        const float* brow0 = ab_sm + (48 + s * 16) * K1_ABS;
        float acc[5] = {0.f, 0.f, 0.f, 0.f, 0.f};
        for (int kk = 0; kk < 16; kk++) {
            const float* ar = arow0 + kk * K1_ABS;
            const float* br = brow0 + kk * K1_ABS;
            #pragma unroll
            for (int dt = 0; dt < TC1; dt++) {
                float bv = br[dt * 25 + lane];
                #pragma unroll
                for (int i = 0; i < 5; i++)
                    acc[i] = fmaf(ar[dt * 25 + v0 + i], bv, acc[i]);
            }
        }
        if (lane < 25) {
            float* dst = g_part + (((size_t)ch * NB + n) * SS + s) * 625;
            #pragma unroll
            for (int i = 0; i < 5; i++)
                dst[(v0 + i) * 25 + lane] = acc[i] * inv;
        }
    }
}

// ============================================================================
// Kernel 2: reduce chunk partials, softmax over v, add A+PA -> g_att
// ============================================================================
__global__ void k2_softmax(const float* __restrict__ A, const float* __restrict__ PA)
{
    const int n = blockIdx.x, s = blockIdx.y;
    __shared__ float sc[625];
    const int tid = threadIdx.x;

    for (int i = tid; i < 625; i += 256) {
        float acc = 0.f;
        for (int ch = 0; ch < NCH1; ch++)
            acc += g_part[(((size_t)ch * NB + n) * SS + s) * 625 + i];
        sc[i] = acc;
    }
    __syncthreads();

    if (tid < 25) {
        const int u = tid;
        float mx = -1e30f;
        #pragma unroll
        for (int v = 0; v < 25; v++) mx = fmaxf(mx, sc[v * 25 + u]);
        float e[25], sum = 0.f;
        #pragma unroll
        for (int v = 0; v < 25; v++) { e[v] = expf(sc[v * 25 + u] - mx); sum += e[v]; }
        const float rs = 1.f / sum;
        #pragma unroll
        for (int v = 0; v < 25; v++) {
            int idx = s * 625 + v * 25 + u;
            g_att[((size_t)n * SS + s) * 625 + v * 25 + u] = e[v] * rs + A[idx] + PA[idx];
        }
    }
}

// ============================================================================
// Kernel 3: phase Y scalar (f32x2), phase Z on tensor cores. (unchanged R8)
// ============================================================================
#define K3_XPAD 28
#define K3_XSTR (TC3 * K3_XPAD)            // 140
#define K3_OFF_X   0
#define K3_OFF_ATT (64 * K3_XSTR)          // 8960
#define K3_OFF_SC  (K3_OFF_ATT + 3 * 632)  // 10856
#define K3_OFF_SH  (K3_OFF_SC + 64)        // 10920
#define K3_OFF_WH  (K3_OFF_SH + 64)        // 10984
#define K3_OFF_WL  (K3_OFF_WH + 2304)
#define K3_OFF_YH  (K3_OFF_WL + 2304)
#define K3_OFF_YL  (K3_OFF_YH + 4608)
#define K3_NF      (K3_OFF_YL + 4608)      // 24808 floats
#define K3_SMEM    (K3_NF * 4)             // 99232 B

__global__ __launch_bounds__(512, 2)
void k3_fused(const float* __restrict__ x, const float* __restrict__ wd,
              const float* __restrict__ bd,
              const float* __restrict__ gma, const float* __restrict__ bta,
              const float* __restrict__ mu,  const float* __restrict__ var,
              float* __restrict__ out)
{
    const int n = blockIdx.x, ch = blockIdx.y, t0 = ch * TC3;
    const int tid = threadIdx.x, lane = tid & 31, wrp = tid >> 5;
    const int quad = lane >> 2, t4 = lane & 3;

    extern __shared__ float sm[];
    float* x_sm   = sm + K3_OFF_X;              // [64][140]
    float* att_sm = sm + K3_OFF_ATT;            // [3][632]
    float* sc_sm  = sm + K3_OFF_SC;             // [64]
    float* sh_sm  = sm + K3_OFF_SH;             // [64]
    __nv_bfloat16* w_hi = (__nv_bfloat16*)(sm + K3_OFF_WH);  // [64][72]
    __nv_bfloat16* w_lo = (__nv_bfloat16*)(sm + K3_OFF_WL);
    __nv_bfloat16* y_hi = (__nv_bfloat16*)(sm + K3_OFF_YH);  // [128][72]
    __nv_bfloat16* y_lo = (__nv_bfloat16*)(sm + K3_OFF_YL);

    const float* xg = x + (size_t)n * 64 * 7500 + (size_t)t0 * 25;
    for (int i = tid; i < 64 * 125; i += 512) {
        int c = i / 125, j = i % 125, dt = j / 25, v = j % 25;
        x_sm[c * K3_XSTR + dt * K3_XPAD + v] = xg[(size_t)c * 7500 + j];
    }
    for (int i = tid; i < SS * 625; i += 512) {
        int s = i / 625, r = i % 625;
        att_sm[s * 632 + r] = g_att[((size_t)n * SS + s) * 625 + r];
    }
    if (tid < 64) {
        float scl = gma[tid] * rsqrtf(var[tid] + 1e-5f);
        float bsum = bd[tid] + bd[64 + tid] + bd[128 + tid];
        sc_sm[tid] = scl;
        sh_sm[tid] = (bsum - mu[tid]) * scl + bta[tid];
    }
    if (tid < 3 * 72) {
        y_hi[125 * 72 + tid] = __float2bfloat16_rn(0.f);
        y_lo[125 * 72 + tid] = __float2bfloat16_rn(0.f);
    }

    const int o0 = (wrp >> 2) * 16;
    const int jg = wrp & 3;
    float d[4][4];
    #pragma unroll
    for (int f = 0; f < 4; f++)
        #pragma unroll
        for (int q = 0; q < 4; q++) d[f][q] = 0.f;

    for (int s = 0; s < SS; s++) {
        __syncthreads();

        for (int i = tid; i < 4096; i += 512) {
            int o = i >> 6, k = i & 63;
            float v = wd[(size_t)s * 4096 + i];
            __nv_bfloat16 h = __float2bfloat16_rn(v);
            w_hi[o * 72 + k] = h;
            w_lo[o * 72 + k] = __float2bfloat16_rn(v - __bfloat162float(h));
        }

        // Phase Y: y[c][j=dt*25+u] = sum_v x[c][dt][v] * att_s[v][u]
        {
            const int u = (lane < 25) ? lane : 24;
            const float* as = att_sm + s * 632;
            u64t ap[12];
            #pragma unroll
            for (int i = 0; i < 12; i++)
                ap[i] = pk2(as[(2 * i) * 25 + u], as[(2 * i + 1) * 25 + u]);
            float a24 = as[600 + u];

            #pragma unroll
            for (int cc = 0; cc < 4; cc++) {
                int c = wrp * 4 + cc;
                #pragma unroll
                for (int dt = 0; dt < TC3; dt++) {
                    const float* xr = x_sm + c * K3_XSTR + dt * K3_XPAD;
                    u64t acc2a = 0ULL, acc2b = 0ULL;
                    #pragma unroll
                    for (int m = 0; m < 6; m += 2) {
                        ulonglong2 xx0 = *(const ulonglong2*)(xr + 4 * m);
                        ulonglong2 xx1 = *(const ulonglong2*)(xr + 4 * m + 4);
                        fma2(acc2a, xx0.x, ap[2 * m]);
                        fma2(acc2b, xx0.y, ap[2 * m + 1]);
                        fma2(acc2a, xx1.x, ap[2 * m + 2]);
                        fma2(acc2b, xx1.y, ap[2 * m + 3]);
                    }
                    float2 fa = up2(acc2a), fb = up2(acc2b);
                    float res = fmaf(xr[24], a24, (fa.x + fb.x) + (fa.y + fb.y));
                    if (lane < 25) {
                        int j = dt * 25 + lane;
                        __nv_bfloat16 h = __float2bfloat16_rn(res);
                        y_hi[j * 72 + c] = h;
                        y_lo[j * 72 + c] = __float2bfloat16_rn(res - __bfloat162float(h));
                    }
                }
            }
        }
        __syncthreads();

        // Phase Z: tensor-core accumulation, K = 64 for this subset
        #pragma unroll
        for (int k0 = 0; k0 < 64; k0 += 16) {
            const int ar0 = (o0 + quad) * 72 + k0 + 2 * t4;
            const int ar1 = (o0 + quad + 8) * 72 + k0 + 2 * t4;
            u32 ah0 = ldb2(w_hi + ar0),     ah1 = ldb2(w_hi + ar1);
            u32 ah2 = ldb2(w_hi + ar0 + 8), ah3 = ldb2(w_hi + ar1 + 8);
            u32 al0 = ldb2(w_lo + ar0),     al1 = ldb2(w_lo + ar1);
            u32 al2 = ldb2(w_lo + ar0 + 8), al3 = ldb2(w_lo + ar1 + 8);
            #pragma unroll
            for (int f = 0; f < 4; f++) {
                int j = jg * 32 + f * 8 + quad;
                int br = j * 72 + k0 + 2 * t4;
                u32 bh0 = ldb2(y_hi + br), bh1 = ldb2(y_hi + br + 8);
                u32 bl0 = ldb2(y_lo + br), bl1 = ldb2(y_lo + br + 8);
                mma_bf16(d[f][0], d[f][1], d[f][2], d[f][3],
                         ah0, ah1, ah2, ah3, bh0, bh1);
                mma_bf16(d[f][0], d[f][1], d[f][2], d[f][3],
                         ah0, ah1, ah2, ah3, bl0, bl1);
                mma_bf16(d[f][0], d[f][1], d[f][2], d[f][3],
                         al0, al1, al2, al3, bh0, bh1);
            }
        }
    }

    // Epilogue: BN + residual + ReLU from D fragments
    float* og = out + (size_t)n * 64 * 7500 + (size_t)t0 * 25;
    #pragma unroll
    for (int f = 0; f < 4; f++) {
        int jb = jg * 32 + f * 8 + 2 * t4;
        #pragma unroll
        for (int h = 0; h < 2; h++) {
            int o = o0 + quad + 8 * h;
            float scl = sc_sm[o], shf = sh_sm[o];
            #pragma unroll
            for (int cc = 0; cc < 2; cc++) {
                int j = jb + cc;
                if (j < 125) {
                    int dt = j / 25, u = j - dt * 25;
                    float r = fmaf(d[f][2 * h + cc], scl, shf)
                              + x_sm[o * K3_XSTR + dt * K3_XPAD + u];
                    og[(size_t)o * 7500 + j] = fmaxf(r, 0.f);
                }
            }
        }
    }
}

// ============================================================================
extern "C" void kernel_launch(void* const* d_in, const int* in_sizes, int n_in,
                              void* d_out, int out_size)
{
    const float* x   = (const float*)d_in[0];
    const float* A   = (const float*)d_in[1];
    const float* PA  = (const float*)d_in[2];
    const float* wa  = (const float*)d_in[3];
    const float* ba  = (const float*)d_in[4];
    const float* wb  = (const float*)d_in[5];
    const float* bb  = (const float*)d_in[6];
    const float* wd  = (const float*)d_in[7];
    const float* bd  = (const float*)d_in[8];
    const float* gma = (const float*)d_in[9];
    const float* bta = (const float*)d_in[10];
    const float* mu  = (const float*)d_in[11];
    const float* var = (const float*)d_in[12];
    float* out = (float*)d_out;

    cudaFuncSetAttribute(k1_scores, cudaFuncAttributeMaxDynamicSharedMemorySize, K1_SMEM);
    cudaFuncSetAttribute(k3_fused,  cudaFuncAttributeMaxDynamicSharedMemorySize, K3_SMEM);

    k1_scores<<<dim3(NB, NCH1), 512, K1_SMEM>>>(x, wa, ba, wb, bb);
    k2_softmax<<<dim3(NB, SS), 256>>>(A, PA);
    k3_fused<<<dim3(NB, NCH3), 512, K3_SMEM>>>(x, wd, bd, gma, bta, mu, var, out);
}

// round 10
// speedup vs baseline: 3.4082x; 1.7161x over previous
#include <cuda_runtime.h>
#include <cuda_bf16.h>
#include <cstdint>
#include <math.h>

typedef unsigned int u32;

// Problem dims (fixed)
#define NB 64
#define TT 300
#define VV 25
#define SS 3

#define TC1 5
#define NCH1 (TT / TC1)          // 60 chunks for k1
#define TC3 5
#define NCH3 (TT / TC3)          // 60 chunks for k3

// Scratch (no allocations allowed)
__device__ float g_part[(size_t)NCH1 * NB * SS * VV * VV];  // 28.8 MB
__device__ float g_att[(size_t)NB * SS * VV * VV];          // 480 KB

// ---- bf16 mma helper -------------------------------------------------------
__device__ __forceinline__ void mma_bf16(float& d0, float& d1, float& d2, float& d3,
                                         u32 a0, u32 a1, u32 a2, u32 a3,
                                         u32 b0, u32 b1) {
    asm("mma.sync.aligned.m16n8k16.row.col.f32.bf16.bf16.f32 "
        "{%0,%1,%2,%3},{%4,%5,%6,%7},{%8,%9},{%0,%1,%2,%3};"
        : "+f"(d0), "+f"(d1), "+f"(d2), "+f"(d3)
        : "r"(a0), "r"(a1), "r"(a2), "r"(a3), "r"(b0), "r"(b1));
}
__device__ __forceinline__ u32 ldb2(const __nv_bfloat16* p) {
    return *reinterpret_cast<const u32*>(p);
}
// word-index swizzle for 16-word (32 bf16) rows: conflict-free frag loads
__device__ __forceinline__ int idx16(int r, int w) {
    return (r << 4) + (w ^ (((r >> 1) & 3) << 2));
}

// ============================================================================
// Kernel 1: conv_a/conv_b AND score accumulation fully on tensor cores.
// Phase 1: ab = W[96x64] @ Xt[128x64]^T (bf16 hi), results stored directly
//          as bf16 into a_t[s][v][m], b_t[s][u][m]  (m = k*5+dt, stride 88).
// Phase 2: scores[s] = a_t @ b_t^T : m16n8k16, M=32, N=32, K=80 exact.
// smem 64.5 KB -> 3 CTAs/SM @ 384 threads.
// ============================================================================
#define K1_OFF_XT 0                       // xt  [128][72] bf16 = 4608 floats
#define K1_OFF_WH 4608                    // wh  [96][72]  bf16 = 3456 floats
#define K1_OFF_AT 8064                    // a_t [3][32][88] bf16 = 4224 floats
#define K1_OFF_BT 12288                   // b_t same
#define K1_NF     16512
#define K1_SMEM   (K1_NF * 4)             // 66048 B

__global__ __launch_bounds__(384, 3)
void k1_scores(const float* __restrict__ x, const float* __restrict__ wa,
               const float* __restrict__ ba, const float* __restrict__ wb,
               const float* __restrict__ bb)
{
    const int n = blockIdx.x, ch = blockIdx.y, t0 = ch * TC1;
    const int tid = threadIdx.x, lane = tid & 31, wrp = tid >> 5;  // 12 warps
    const int quad = lane >> 2, t4 = lane & 3;

    extern __shared__ float sm[];
    __nv_bfloat16* xt = (__nv_bfloat16*)(sm + K1_OFF_XT);   // [j][c] stride 72
    __nv_bfloat16* wh = (__nv_bfloat16*)(sm + K1_OFF_WH);   // [row][k] stride 72
    __nv_bfloat16* at = (__nv_bfloat16*)(sm + K1_OFF_AT);   // [s][v][m] stride 88
    __nv_bfloat16* bt = (__nv_bfloat16*)(sm + K1_OFF_BT);

    // stage weights (hi only) and x (bf16 hi, transposed)
    for (int i = tid; i < 96 * 64; i += 384) {
        int row = i >> 6, k = i & 63;
        float v = (row < 48) ? wa[row * 64 + k] : wb[(row - 48) * 64 + k];
        wh[row * 72 + k] = __float2bfloat16_rn(v);
    }
    const float* xg = x + (size_t)n * 64 * 7500 + (size_t)t0 * 25;
    for (int i = tid; i < 64 * 128; i += 384) {
        int c = i >> 7, j = i & 127;
        float v = (j < 125) ? xg[(size_t)c * 7500 + j] : 0.f;
        xt[j * 72 + c] = __float2bfloat16_rn(v);
    }
    __syncthreads();

    // Phase 1: 48 mma jobs (6 m-tiles x 8 n-tiles), 4 per warp.
    #pragma unroll
    for (int jj = 0; jj < 4; jj++) {
        const int job = wrp + 12 * jj;
        const int mi = job >> 3, nq = job & 7;
        const int r0 = mi * 16 + quad;

        float d[2][4];
        #pragma unroll
        for (int h = 0; h < 2; h++)
            #pragma unroll
            for (int q = 0; q < 4; q++) d[h][q] = 0.f;

        #pragma unroll
        for (int ks = 0; ks < 4; ks++) {
            const int ka = ks * 16 + 2 * t4;
            u32 a0 = ldb2(wh + r0 * 72 + ka);
            u32 a1 = ldb2(wh + (r0 + 8) * 72 + ka);
            u32 a2 = ldb2(wh + r0 * 72 + ka + 8);
            u32 a3 = ldb2(wh + (r0 + 8) * 72 + ka + 8);
            #pragma unroll
            for (int h = 0; h < 2; h++) {
                int jc = nq * 16 + h * 8 + quad;
                u32 b0 = ldb2(xt + jc * 72 + ka);
                u32 b1 = ldb2(xt + jc * 72 + ka + 8);
                mma_bf16(d[h][0], d[h][1], d[h][2], d[h][3], a0, a1, a2, a3, b0, b1);
            }
        }

        // epilogue: bias + direct bf16 scatter into a_t / b_t
        const int ra = r0, rb = r0 + 8;
        const float biasA = (ra < 48) ? ba[ra] : bb[ra - 48];
        const float biasB = (rb < 48) ? ba[rb] : bb[rb - 48];
        #pragma unroll
        for (int h = 0; h < 2; h++) {
            #pragma unroll
            for (int cc = 0; cc < 2; cc++) {
                int col = nq * 16 + h * 8 + 2 * t4 + cc;
                if (col < 125) {
                    int dt = col / 25, v = col - dt * 25;
                    {   // row ra
                        float val = d[h][cc] + biasA;
                        if (ra < 48)
                            at[(ra >> 4) * 2816 + v * 88 + (ra & 15) * 5 + dt] =
                                __float2bfloat16_rn(val);
                        else {
                            int r2 = ra - 48;
                            bt[(r2 >> 4) * 2816 + v * 88 + (r2 & 15) * 5 + dt] =
                                __float2bfloat16_rn(val);
                        }
                    }
                    {   // row rb
                        float val = d[h][2 + cc] + biasB;
                        if (rb < 48)
                            at[(rb >> 4) * 2816 + v * 88 + (rb & 15) * 5 + dt] =
                                __float2bfloat16_rn(val);
                        else {
                            int r2 = rb - 48;
                            bt[(r2 >> 4) * 2816 + v * 88 + (r2 & 15) * 5 + dt] =
                                __float2bfloat16_rn(val);
                        }
                    }
                }
            }
        }
    }
    __syncthreads();

    // Phase 2: scores via mma. 24 jobs (3 s x 2 v-tiles x 4 u-tiles), 2/warp.
    const float inv = 1.0f / 4800.0f;
    #pragma unroll
    for (int jj = 0; jj < 2; jj++) {
        const int job = wrp + 12 * jj;
        const int s = job >> 3, r = job & 7, mt = r >> 2, nt = r & 3;
        const int v0 = mt * 16 + quad;
        const int u0 = nt * 8 + quad;
        const __nv_bfloat16* as_ = at + s * 2816;
        const __nv_bfloat16* bs_ = bt + s * 2816;

        float d0 = 0.f, d1 = 0.f, d2 = 0.f, d3 = 0.f;
        #pragma unroll
        for (int ks = 0; ks < 5; ks++) {
            const int me = 2 * t4 + 16 * ks;
            u32 a0 = ldb2(as_ + v0 * 88 + me);
            u32 a1 = ldb2(as_ + (v0 + 8) * 88 + me);
            u32 a2 = ldb2(as_ + v0 * 88 + me + 8);
            u32 a3 = ldb2(as_ + (v0 + 8) * 88 + me + 8);
            u32 b0 = ldb2(bs_ + u0 * 88 + me);
            u32 b1 = ldb2(bs_ + u0 * 88 + me + 8);
            mma_bf16(d0, d1, d2, d3, a0, a1, a2, a3, b0, b1);
        }

        float* dst = g_part + (((size_t)ch * NB + n) * SS + s) * 625;
        const int uA = nt * 8 + 2 * t4, uB = uA + 1;
        const int vA = v0, vB = v0 + 8;
        if (vA < 25) {
            if (uA < 25) dst[vA * 25 + uA] = d0 * inv;
            if (uB < 25) dst[vA * 25 + uB] = d1 * inv;
        }
        if (vB < 25) {
            if (uA < 25) dst[vB * 25 + uA] = d2 * inv;
            if (uB < 25) dst[vB * 25 + uB] = d3 * inv;
        }
    }
}

// ============================================================================
// Kernel 2: reduce chunk partials, softmax over v, add A+PA -> g_att
// ============================================================================
__global__ void k2_softmax(const float* __restrict__ A, const float* __restrict__ PA)
{
    const int n = blockIdx.x, s = blockIdx.y;
    __shared__ float sc[625];
    const int tid = threadIdx.x;

    for (int i = tid; i < 625; i += 256) {
        float acc = 0.f;
        for (int ch = 0; ch < NCH1; ch++)
            acc += g_part[(((size_t)ch * NB + n) * SS + s) * 625 + i];
        sc[i] = acc;
    }
    __syncthreads();

    if (tid < 25) {
        const int u = tid;
        float mx = -1e30f;
        #pragma unroll
        for (int v = 0; v < 25; v++) mx = fmaxf(mx, sc[v * 25 + u]);
        float e[25], sum = 0.f;
        #pragma unroll
        for (int v = 0; v < 25; v++) { e[v] = expf(sc[v * 25 + u] - mx); sum += e[v]; }
        const float rs = 1.f / sum;
        #pragma unroll
        for (int v = 0; v < 25; v++) {
            int idx = s * 625 + v * 25 + u;
            g_att[((size_t)n * SS + s) * 625 + v * 25 + u] = e[v] * rs + A[idx] + PA[idx];
        }
    }
}

// ============================================================================
// Kernel 3: BOTH phase Y (x@att) and phase Z (conv_d) on tensor cores.
// Phase Y: D[m=(c,dt)][u] = X[320x32] @ attT, 2-term hi/lo split both sides
// (xh*ah + xh*al + xl*ah). x stored once as hi/lo bf16 [m][32] XOR-swizzled;
// residual reconstructed as hi+lo. Phase Z as R8 (w/y stride 72, 3-term).
// smem 109 KB -> 2 CTAs/SM.
// ============================================================================
#define K3_OFF_XTH 0                      // [320][32] bf16 = 5120 f
#define K3_OFF_XTL 5120
#define K3_OFF_ATH 10240                  // [3][32][32] bf16 = 1536 f
#define K3_OFF_ATL 11776
#define K3_OFF_YH  13312                  // [128][72] bf16 = 4608 f
#define K3_OFF_YL  17920
#define K3_OFF_WH  22528                  // [64][72] bf16 = 2304 f
#define K3_OFF_WL  24832
#define K3_OFF_SC  27136
#define K3_OFF_SH  27200
#define K3_NF      27264
#define K3_SMEM    (K3_NF * 4)            // 109056 B

__global__ __launch_bounds__(512, 2)
void k3_fused(const float* __restrict__ x, const float* __restrict__ wd,
              const float* __restrict__ bd,
              const float* __restrict__ gma, const float* __restrict__ bta,
              const float* __restrict__ mu,  const float* __restrict__ var,
              float* __restrict__ out)
{
    const int n = blockIdx.x, ch = blockIdx.y, t0 = ch * TC3;
    const int tid = threadIdx.x, lane = tid & 31, wrp = tid >> 5;
    const int quad = lane >> 2, t4 = lane & 3;

    extern __shared__ float sm[];
    u32* xthw = (u32*)(sm + K3_OFF_XTH);   // [320][16 words] swizzled
    u32* xtlw = (u32*)(sm + K3_OFF_XTL);
    u32* athw = (u32*)(sm + K3_OFF_ATH);   // [3][32][16 words] swizzled
    u32* atlw = (u32*)(sm + K3_OFF_ATL);
    __nv_bfloat16* xth_b = (__nv_bfloat16*)(sm + K3_OFF_XTH);
    __nv_bfloat16* xtl_b = (__nv_bfloat16*)(sm + K3_OFF_XTL);
    __nv_bfloat16* y_hi = (__nv_bfloat16*)(sm + K3_OFF_YH);  // [128][72]
    __nv_bfloat16* y_lo = (__nv_bfloat16*)(sm + K3_OFF_YL);
    __nv_bfloat16* w_hi = (__nv_bfloat16*)(sm + K3_OFF_WH);  // [64][72]
    __nv_bfloat16* w_lo = (__nv_bfloat16*)(sm + K3_OFF_WL);
    float* sc_sm = sm + K3_OFF_SC;
    float* sh_sm = sm + K3_OFF_SH;

    // ---- stage x as hi/lo bf16 pairs, [m=(c*5+dt)][v], swizzled ------------
    const float* xg = x + (size_t)n * 64 * 7500 + (size_t)t0 * 25;
    for (int i = tid; i < 320 * 16; i += 512) {
        int m = i >> 4, w = i & 15;
        int c = m / 5, dt = m - 5 * c;
        int v0 = 2 * w;
        float f0 = (v0 < 25)     ? xg[(size_t)c * 7500 + dt * 25 + v0]     : 0.f;
        float f1 = (v0 + 1 < 25) ? xg[(size_t)c * 7500 + dt * 25 + v0 + 1] : 0.f;
        __nv_bfloat16 h0 = __float2bfloat16_rn(f0);
        __nv_bfloat16 h1 = __float2bfloat16_rn(f1);
        __nv_bfloat16 l0 = __float2bfloat16_rn(f0 - __bfloat162float(h0));
        __nv_bfloat16 l1 = __float2bfloat16_rn(f1 - __bfloat162float(h1));
        int a = idx16(m, w);
        xthw[a] = ((u32)*(unsigned short*)&h1 << 16) | *(unsigned short*)&h0;
        xtlw[a] = ((u32)*(unsigned short*)&l1 << 16) | *(unsigned short*)&l0;
    }
    // ---- stage att transposed [s][u][v], hi/lo, swizzled -------------------
    for (int i = tid; i < 3 * 512; i += 512) {
        int s = i >> 9, rem = i & 511;
        int u = rem >> 4, w = rem & 15;
        int v0 = 2 * w;
        const float* ag = g_att + ((size_t)n * SS + s) * 625;
        float f0 = (u < 25 && v0 < 25)     ? ag[v0 * 25 + u]       : 0.f;
        float f1 = (u < 25 && v0 + 1 < 25) ? ag[(v0 + 1) * 25 + u] : 0.f;
        __nv_bfloat16 h0 = __float2bfloat16_rn(f0);
        __nv_bfloat16 h1 = __float2bfloat16_rn(f1);
        __nv_bfloat16 l0 = __float2bfloat16_rn(f0 - __bfloat162float(h0));
        __nv_bfloat16 l1 = __float2bfloat16_rn(f1 - __bfloat162float(h1));
        int a = s * 512 + idx16(u, w);
        athw[a] = ((u32)*(unsigned short*)&h1 << 16) | *(unsigned short*)&h0;
        atlw[a] = ((u32)*(unsigned short*)&l1 << 16) | *(unsigned short*)&l0;
    }
    if (tid < 64) {
        float scl = gma[tid] * rsqrtf(var[tid] + 1e-5f);
        float bsum = bd[tid] + bd[64 + tid] + bd[128 + tid];
        sc_sm[tid] = scl;
        sh_sm[tid] = (bsum - mu[tid]) * scl + bta[tid];
    }
    if (tid < 3 * 72) {  // zero y rows j=125..127 (N-padding for phase Z)
        y_hi[125 * 72 + tid] = __float2bfloat16_rn(0.f);
        y_lo[125 * 72 + tid] = __float2bfloat16_rn(0.f);
    }

    // warp tiles: phase Y uses (mg, nt); phase Z uses (o0, jg) from same wrp
    const int mg = wrp >> 2, nt = wrp & 3;
    const int o0 = mg * 16, jg = nt;
    float dz[4][4];
    #pragma unroll
    for (int f = 0; f < 4; f++)
        #pragma unroll
        for (int q = 0; q < 4; q++) dz[f][q] = 0.f;

    for (int s = 0; s < SS; s++) {
        __syncthreads();   // prev phase Z done with w/y; covers init on s=0

        // stage this subset's conv_d weights hi/lo (stride 72)
        for (int i = tid; i < 4096; i += 512) {
            int o = i >> 6, k = i & 63;
            float v = wd[(size_t)s * 4096 + i];
            __nv_bfloat16 h = __float2bfloat16_rn(v);
            w_hi[o * 72 + k] = h;
            w_lo[o * 72 + k] = __float2bfloat16_rn(v - __bfloat162float(h));
        }

        // ---- Phase Y (tensor cores): D[m][u] over K=v=32 -------------------
        {
            // hoist att B-frags for this warp's u-tile (8 regs)
            const int u = nt * 8 + quad;
            u32 bh[2][2], bl[2][2];
            #pragma unroll
            for (int ks = 0; ks < 2; ks++) {
                bh[ks][0] = athw[s * 512 + idx16(u, t4 + 8 * ks)];
                bh[ks][1] = athw[s * 512 + idx16(u, t4 + 4 + 8 * ks)];
                bl[ks][0] = atlw[s * 512 + idx16(u, t4 + 8 * ks)];
                bl[ks][1] = atlw[s * 512 + idx16(u, t4 + 4 + 8 * ks)];
            }
            #pragma unroll
            for (int q = 0; q < 5; q++) {
                const int mt = mg * 5 + q;
                const int m0 = mt * 16 + quad, m1 = m0 + 8;
                float D0 = 0.f, D1 = 0.f, D2 = 0.f, D3 = 0.f;
                #pragma unroll
                for (int ks = 0; ks < 2; ks++) {
                    u32 ah0 = xthw[idx16(m0, t4 + 8 * ks)];
                    u32 ah1 = xthw[idx16(m1, t4 + 8 * ks)];
                    u32 ah2 = xthw[idx16(m0, t4 + 4 + 8 * ks)];
                    u32 ah3 = xthw[idx16(m1, t4 + 4 + 8 * ks)];
                    u32 al0 = xtlw[idx16(m0, t4 + 8 * ks)];
                    u32 al1 = xtlw[idx16(m1, t4 + 8 * ks)];
                    u32 al2 = xtlw[idx16(m0, t4 + 4 + 8 * ks)];
                    u32 al3 = xtlw[idx16(m1, t4 + 4 + 8 * ks)];
                    mma_bf16(D0, D1, D2, D3, ah0, ah1, ah2, ah3, bh[ks][0], bh[ks][1]);
                    mma_bf16(D0, D1, D2, D3, ah0, ah1, ah2, ah3, bl[ks][0], bl[ks][1]);
                    mma_bf16(D0, D1, D2, D3, al0, al1, al2, al3, bh[ks][0], bh[ks][1]);
                }
                // scatter y hi/lo: (m, u) -> y_t[j = dt*25+u][c]
                const int u0 = nt * 8 + 2 * t4;
                #pragma unroll
                for (int cc = 0; cc < 2; cc++) {
                    int uu = u0 + cc;
                    if (uu < 25) {
                        {
                            int c = m0 / 5, dt = m0 - 5 * c;
                            int j = dt * 25 + uu;
                            float val = cc ? D1 : D0;
                            __nv_bfloat16 h = __float2bfloat16_rn(val);
                            y_hi[j * 72 + c] = h;
                            y_lo[j * 72 + c] = __float2bfloat16_rn(val - __bfloat162float(h));
                        }
                        {
                            int c = m1 / 5, dt = m1 - 5 * c;
                            int j = dt * 25 + uu;
                            float val = cc ? D3 : D2;
                            __nv_bfloat16 h = __float2bfloat16_rn(val);
                            y_hi[j * 72 + c] = h;
                            y_lo[j * 72 + c] = __float2bfloat16_rn(val - __bfloat162float(h));
                        }
                    }
                }
            }
        }
        __syncthreads();

        // ---- Phase Z (tensor cores): z += wd_s @ y_s, K=64 -----------------
        #pragma unroll
        for (int k0 = 0; k0 < 64; k0 += 16) {
            const int ar0 = (o0 + quad) * 72 + k0 + 2 * t4;
            const int ar1 = (o0 + quad + 8) * 72 + k0 + 2 * t4;
            u32 ah0 = ldb2(w_hi + ar0),     ah1 = ldb2(w_hi + ar1);
            u32 ah2 = ldb2(w_hi + ar0 + 8), ah3 = ldb2(w_hi + ar1 + 8);
            u32 al0 = ldb2(w_lo + ar0),     al1 = ldb2(w_lo + ar1);
            u32 al2 = ldb2(w_lo + ar0 + 8), al3 = ldb2(w_lo + ar1 + 8);
            #pragma unroll
            for (int f = 0; f < 4; f++) {
                int j = jg * 32 + f * 8 + quad;
                int br = j * 72 + k0 + 2 * t4;
                u32 bh0 = ldb2(y_hi + br), bh1 = ldb2(y_hi + br + 8);
                u32 bl0 = ldb2(y_lo + br), bl1 = ldb2(y_lo + br + 8);
                mma_bf16(dz[f][0], dz[f][1], dz[f][2], dz[f][3],
                         ah0, ah1, ah2, ah3, bh0, bh1);
                mma_bf16(dz[f][0], dz[f][1], dz[f][2], dz[f][3],
                         ah0, ah1, ah2, ah3, bl0, bl1);
                mma_bf16(dz[f][0], dz[f][1], dz[f][2], dz[f][3],
                         al0, al1, al2, al3, bh0, bh1);
            }
        }
    }

    // ---- epilogue: BN + residual (x = hi+lo) + ReLU ------------------------
    float* og = out + (size_t)n * 64 * 7500 + (size_t)t0 * 25;
    #pragma unroll
    for (int f = 0; f < 4; f++) {
        int jb = jg * 32 + f * 8 + 2 * t4;
        #pragma unroll
        for (int h = 0; h < 2; h++) {
            int o = o0 + quad + 8 * h;
            float scl = sc_sm[o], shf = sh_sm[o];
            #pragma unroll
            for (int cc = 0; cc < 2; cc++) {
                int j = jb + cc;
                if (j < 125) {
                    int dt = j / 25, u = j - dt * 25;
                    int r2 = o * 5 + dt;
                    int ew = 2 * idx16(r2, u >> 1) + (u & 1);
                    float xv = __bfloat162float(xth_b[ew]) + __bfloat162float(xtl_b[ew]);
                    float r = fmaf(dz[f][2 * h + cc], scl, shf) + xv;
                    og[(size_t)o * 7500 + j] = fmaxf(r, 0.f);
                }
            }
        }
    }
}

// ============================================================================
extern "C" void kernel_launch(void* const* d_in, const int* in_sizes, int n_in,
                              void* d_out, int out_size)
{
    const float* x   = (const float*)d_in[0];
    const float* A   = (const float*)d_in[1];
    const float* PA  = (const float*)d_in[2];
    const float* wa  = (const float*)d_in[3];
    const float* ba  = (const float*)d_in[4];
    const float* wb  = (const float*)d_in[5];
    const float* bb  = (const float*)d_in[6];
    const float* wd  = (const float*)d_in[7];
    const float* bd  = (const float*)d_in[8];
    const float* gma = (const float*)d_in[9];
    const float* bta = (const float*)d_in[10];
    const float* mu  = (const float*)d_in[11];
    const float* var = (const float*)d_in[12];
    float* out = (float*)d_out;

    cudaFuncSetAttribute(k1_scores, cudaFuncAttributeMaxDynamicSharedMemorySize, K1_SMEM);
    cudaFuncSetAttribute(k3_fused,  cudaFuncAttributeMaxDynamicSharedMemorySize, K3_SMEM);

    k1_scores<<<dim3(NB, NCH1), 384, K1_SMEM>>>(x, wa, ba, wb, bb);
    k2_softmax<<<dim3(NB, SS), 256>>>(A, PA);
    k3_fused<<<dim3(NB, NCH3), 512, K3_SMEM>>>(x, wd, bd, gma, bta, mu, var, out);
}